// round 1
// baseline (speedup 1.0000x reference)
#include <cuda_runtime.h>
#include <math.h>

// Problem constants
#define Bsz  4096
#define Dd   256
#define Hh   256
#define Ss   3
#define REPT 10
#define OUTN 44
#define SH   768      // S*H
#define NZ   1027     // concat input-gate rows: f,i,o,c (4*256) + g (3)
#define NU   768      // concat recurrent-gate rows: f,i,o
#define NG   771      // g-logits (3) + aux (768)
#define FEATK 2304    // (REP-1)*H

// ---------------- scratch (static device allocations; no cudaMalloc) -------
__device__ float g_h[(size_t)Bsz * SH];          // hidden state, [B][S][H]
__device__ float g_c[(size_t)Bsz * SH];          // cell state,   [B][S][H]
__device__ float g_U[(size_t)Ss * Bsz * NU];     // recurrent f,i,o preacts
__device__ float g_AG[(size_t)Ss * Bsz * NG];    // g-logit part2 + aux rows
__device__ float g_Z[(size_t)Bsz * NZ];          // per-layer input preacts
__device__ float g_feat[(size_t)Bsz * FEATK];    // output features
__device__ float g_WiAll[(size_t)Ss * NZ * Dd];
__device__ float g_biAll[Ss * NZ];
__device__ float g_Whfio[(size_t)Ss * NU * Hh];
__device__ float g_bhfio[Ss * NU];
__device__ float g_Whgc[(size_t)Ss * NG * SH];
__device__ float g_bhgc[Ss * NG];

// ---------------- f32x2 packed-FMA helpers ---------------------------------
#define PACKX2(d, lo, hi) asm("mov.b64 %0, {%1, %2};" : "=l"(d) : "f"(lo), "f"(hi))
#define FMAX2(c, a, b)    asm("fma.rn.f32x2 %0, %1, %2, %0;" : "+l"(c) : "l"(a), "l"(b))
#define UNPACKX2(lo, hi, v) asm("mov.b64 {%0, %1}, %2;" : "=f"(lo), "=f"(hi) : "l"(v))

__device__ __forceinline__ float sigf(float x) { return 1.0f / (1.0f + expf(-x)); }

// ---------------- generic tiled GEMM:  C = A @ W^T + bias ------------------
// A: [M x K] row-major (row stride lda), W: [N x K] row-major (row stride K).
// Batched over blockIdx.z via element strides sA/sW/sBias/sC.
// M is always 4096 (gridDim.y * 128). N may be ragged. K % 16 == 0.
#define BM 128
#define BN 128
#define BK 16

__global__ void __launch_bounds__(256, 2)
gemm_nt(const float* __restrict__ A, int lda, long sA,
        const float* __restrict__ W, long sW,
        const float* __restrict__ bias, int sBias,
        float* __restrict__ C, int ldc, long sC,
        int N, int K, int act)
{
    __shared__ __align__(16) float As[BK][BM];
    __shared__ __align__(16) float Ws[BK][BN];

    const int z = blockIdx.z;
    A += (size_t)z * sA;
    W += (size_t)z * sW;
    C += (size_t)z * sC;
    if (bias) bias += (size_t)z * sBias;

    const int m0  = blockIdx.y * BM;
    const int n0  = blockIdx.x * BN;
    const int tid = threadIdx.x;
    const int tx  = tid & 15;
    const int ty  = tid >> 4;

    unsigned long long acc[8][4];
#pragma unroll
    for (int i = 0; i < 8; i++)
#pragma unroll
        for (int j = 0; j < 4; j++) acc[i][j] = 0ull;

    const int ar0 = tid >> 2;        // 0..63 (+64 on second iter)
    const int aq  = (tid & 3) * 4;   // k sub-offset: 0,4,8,12

    for (int k0 = 0; k0 < K; k0 += BK) {
        // stage A tile (M always in range)
#pragma unroll
        for (int i = 0; i < 2; i++) {
            int row = ar0 + i * 64;
            const float4 a4 = *(const float4*)(A + (size_t)(m0 + row) * lda + k0 + aq);
            As[aq + 0][row] = a4.x; As[aq + 1][row] = a4.y;
            As[aq + 2][row] = a4.z; As[aq + 3][row] = a4.w;
        }
        // stage W tile (ragged N -> zero fill)
#pragma unroll
        for (int i = 0; i < 2; i++) {
            int r = ar0 + i * 64;
            int n = n0 + r;
            float4 w4 = make_float4(0.f, 0.f, 0.f, 0.f);
            if (n < N) w4 = *(const float4*)(W + (size_t)n * K + k0 + aq);
            Ws[aq + 0][r] = w4.x; Ws[aq + 1][r] = w4.y;
            Ws[aq + 2][r] = w4.z; Ws[aq + 3][r] = w4.w;
        }
        __syncthreads();

#pragma unroll
        for (int k = 0; k < BK; k++) {
            const float4 a0 = *(const float4*)&As[k][ty * 8];
            const float4 a1 = *(const float4*)&As[k][ty * 8 + 4];
            const float4 b0 = *(const float4*)&Ws[k][tx * 8];
            const float4 b1 = *(const float4*)&Ws[k][tx * 8 + 4];
            unsigned long long bp[4];
            PACKX2(bp[0], b0.x, b0.y); PACKX2(bp[1], b0.z, b0.w);
            PACKX2(bp[2], b1.x, b1.y); PACKX2(bp[3], b1.z, b1.w);
            const float av[8] = {a0.x, a0.y, a0.z, a0.w, a1.x, a1.y, a1.z, a1.w};
#pragma unroll
            for (int i = 0; i < 8; i++) {
                unsigned long long ad;
                PACKX2(ad, av[i], av[i]);
#pragma unroll
                for (int j = 0; j < 4; j++) FMAX2(acc[i][j], ad, bp[j]);
            }
        }
        __syncthreads();
    }

    // epilogue
#pragma unroll
    for (int i = 0; i < 8; i++) {
        const int m = m0 + ty * 8 + i;
#pragma unroll
        for (int j = 0; j < 4; j++) {
            float c0, c1;
            UNPACKX2(c0, c1, acc[i][j]);
            const int n = n0 + tx * 8 + j * 2;
            if (n < N) {
                float v = c0 + (bias ? bias[n] : 0.f);
                if (act) v = sigf(v);
                C[(size_t)m * ldc + n] = v;
            }
            if (n + 1 < N) {
                float v = c1 + (bias ? bias[n + 1] : 0.f);
                if (act) v = sigf(v);
                C[(size_t)m * ldc + n + 1] = v;
            }
        }
    }
}

// ---------------- state init: [S,B,H] -> [B,S,H] ---------------------------
__global__ void init_state(const float* __restrict__ hid, const float* __restrict__ cur,
                           float* __restrict__ h, float* __restrict__ c)
{
    int i = blockIdx.x * blockDim.x + threadIdx.x;
    const int total = Ss * Bsz * Hh;
    if (i >= total) return;
    int l = i / (Bsz * Hh);
    int r = i - l * (Bsz * Hh);
    int b = r >> 8;
    int j = r & 255;
    size_t dst = (size_t)b * SH + l * Hh + j;
    h[dst] = hid[i];
    c[dst] = cur[i];
}

// ---------------- weight repacks -------------------------------------------
__global__ void repack_wi(const float* __restrict__ wf, const float* __restrict__ wi,
                          const float* __restrict__ wo, const float* __restrict__ wc,
                          const float* __restrict__ wg, float* __restrict__ out)
{
    int idx = blockIdx.x * blockDim.x + threadIdx.x;
    if (idx >= Ss * NZ * Dd) return;
    int k = idx % Dd;
    int r = (idx / Dd) % NZ;
    int l = idx / (Dd * NZ);
    float v;
    if      (r < 256)  v = wf[((size_t)l * Hh + r)        * Dd + k];
    else if (r < 512)  v = wi[((size_t)l * Hh + r - 256)  * Dd + k];
    else if (r < 768)  v = wo[((size_t)l * Hh + r - 512)  * Dd + k];
    else if (r < 1024) v = wc[((size_t)l * Hh + r - 768)  * Dd + k];
    else               v = wg[((size_t)l * Ss + r - 1024) * Dd + k];
    out[idx] = v;
}

__global__ void repack_whfio(const float* __restrict__ wf, const float* __restrict__ wi,
                             const float* __restrict__ wo, float* __restrict__ out)
{
    int idx = blockIdx.x * blockDim.x + threadIdx.x;
    if (idx >= Ss * NU * Hh) return;
    int k = idx % Hh;
    int r = (idx / Hh) % NU;
    int l = idx / (Hh * NU);
    float v;
    if      (r < 256) v = wf[((size_t)l * Hh + r)       * Hh + k];
    else if (r < 512) v = wi[((size_t)l * Hh + r - 256) * Hh + k];
    else              v = wo[((size_t)l * Hh + r - 512) * Hh + k];
    out[idx] = v;
}

__global__ void repack_whgc(const float* __restrict__ wg, const float* __restrict__ wc,
                            float* __restrict__ out)
{
    int idx = blockIdx.x * blockDim.x + threadIdx.x;
    if (idx >= Ss * NG * SH) return;
    int k = idx % SH;
    int r = (idx / SH) % NG;
    int l = idx / (SH * NG);
    float v;
    if (r < 3) v = wg[((size_t)l * Ss + r)      * SH + k];
    else       v = wc[((size_t)l * SH + r - 3)  * SH + k];
    out[idx] = v;
}

__global__ void repack_bias(const float* __restrict__ bif, const float* __restrict__ bii,
                            const float* __restrict__ bio, const float* __restrict__ bic,
                            const float* __restrict__ big,
                            const float* __restrict__ bhf, const float* __restrict__ bhi,
                            const float* __restrict__ bho, const float* __restrict__ bhg,
                            const float* __restrict__ bhc,
                            float* __restrict__ biAll, float* __restrict__ bhfio,
                            float* __restrict__ bhgc)
{
    int idx = blockIdx.x * blockDim.x + threadIdx.x;
    const int n1 = Ss * NZ;          // 3081
    const int n2 = n1 + Ss * NU;     // +2304
    const int n3 = n2 + Ss * NG;     // +2313
    if (idx < n1) {
        int r = idx % NZ, l = idx / NZ;
        float v;
        if      (r < 256)  v = bif[l * Hh + r];
        else if (r < 512)  v = bii[l * Hh + r - 256];
        else if (r < 768)  v = bio[l * Hh + r - 512];
        else if (r < 1024) v = bic[l * Hh + r - 768];
        else               v = big[l * Ss + r - 1024];
        biAll[idx] = v;
    } else if (idx < n2) {
        int t = idx - n1;
        int r = t % NU, l = t / NU;
        float v;
        if      (r < 256) v = bhf[l * Hh + r];
        else if (r < 512) v = bhi[l * Hh + r - 256];
        else              v = bho[l * Hh + r - 512];
        bhfio[t] = v;
    } else if (idx < n3) {
        int t = idx - n2;
        int r = t % NG, l = t / NG;
        bhgc[t] = (r < 3) ? bhg[l * Ss + r] : bhc[l * SH + r - 3];
    }
}

// ---------------- per-layer LSTM cell (elementwise + tiny g-gated sum) -----
__global__ void cell_kernel(const float* __restrict__ Z, const float* __restrict__ U,
                            const float* __restrict__ AG,
                            float* __restrict__ h, float* __restrict__ c,
                            float* __restrict__ feat, int l)
{
    int idx = blockIdx.x * blockDim.x + threadIdx.x;
    if (idx >= Bsz * Hh) return;
    int b = idx >> 8;
    int j = idx & 255;
    const float* Zb = Z + (size_t)b * NZ;
    const float* Ub = U + (size_t)b * NU;
    const float* Gb = AG + (size_t)b * NG;

    float g0 = sigf(Zb[1024] + Gb[0]);
    float g1 = sigf(Zb[1025] + Gb[1]);
    float g2 = sigf(Zb[1026] + Gb[2]);
    float aux = g0 * Gb[3 + j] + g1 * Gb[3 + 256 + j] + g2 * Gb[3 + 512 + j];

    float fg = sigf(Zb[j]       + Ub[j]);
    float ig = sigf(Zb[256 + j] + Ub[256 + j]);
    float og = sigf(Zb[512 + j] + Ub[512 + j]);
    float ct = tanhf(Zb[768 + j] + aux);

    size_t sidx = (size_t)b * SH + l * Hh + j;
    float cn = fg * c[sidx] + ig * ct;
    float hn = og * cn;
    c[sidx] = cn;
    h[sidx] = hn;
    if (feat) feat[(size_t)b * FEATK + j] = hn;
}

// ---------------- orchestration --------------------------------------------
extern "C" void kernel_launch(void* const* d_in, const int* in_sizes, int n_in,
                              void* d_out, int out_size)
{
    (void)in_sizes; (void)n_in; (void)out_size;
    const float* x    = (const float*)d_in[0];
    const float* hid0 = (const float*)d_in[1];
    const float* cur0 = (const float*)d_in[2];
    const float* Wi_f = (const float*)d_in[3];
    const float* bi_f = (const float*)d_in[4];
    const float* Wi_i = (const float*)d_in[5];
    const float* bi_i = (const float*)d_in[6];
    const float* Wi_o = (const float*)d_in[7];
    const float* bi_o = (const float*)d_in[8];
    const float* Wi_c = (const float*)d_in[9];
    const float* bi_c = (const float*)d_in[10];
    const float* Wi_g = (const float*)d_in[11];
    const float* bi_g = (const float*)d_in[12];
    const float* Wh_f = (const float*)d_in[13];
    const float* bh_f = (const float*)d_in[14];
    const float* Wh_i = (const float*)d_in[15];
    const float* bh_i = (const float*)d_in[16];
    const float* Wh_o = (const float*)d_in[17];
    const float* bh_o = (const float*)d_in[18];
    const float* Wh_g = (const float*)d_in[19];
    const float* bh_g = (const float*)d_in[20];
    const float* Wh_c = (const float*)d_in[21];
    const float* bh_c = (const float*)d_in[22];
    const float* W_last = (const float*)d_in[23];
    const float* b_last = (const float*)d_in[24];
    float* out = (float*)d_out;

    float *h, *c, *U, *AG, *Z, *feat, *WiAll, *biAll, *Whfio, *bhfio, *Whgc, *bhgc;
    cudaGetSymbolAddress((void**)&h,     g_h);
    cudaGetSymbolAddress((void**)&c,     g_c);
    cudaGetSymbolAddress((void**)&U,     g_U);
    cudaGetSymbolAddress((void**)&AG,    g_AG);
    cudaGetSymbolAddress((void**)&Z,     g_Z);
    cudaGetSymbolAddress((void**)&feat,  g_feat);
    cudaGetSymbolAddress((void**)&WiAll, g_WiAll);
    cudaGetSymbolAddress((void**)&biAll, g_biAll);
    cudaGetSymbolAddress((void**)&Whfio, g_Whfio);
    cudaGetSymbolAddress((void**)&bhfio, g_bhfio);
    cudaGetSymbolAddress((void**)&Whgc,  g_Whgc);
    cudaGetSymbolAddress((void**)&bhgc,  g_bhgc);

    const dim3 blk(256);

    init_state<<<(Ss * Bsz * Hh + 255) / 256, blk>>>(hid0, cur0, h, c);
    repack_wi<<<(Ss * NZ * Dd + 255) / 256, blk>>>(Wi_f, Wi_i, Wi_o, Wi_c, Wi_g, WiAll);
    repack_whfio<<<(Ss * NU * Hh + 255) / 256, blk>>>(Wh_f, Wh_i, Wh_o, Whfio);
    repack_whgc<<<(Ss * NG * SH + 255) / 256, blk>>>(Wh_g, Wh_c, Whgc);
    repack_bias<<<(Ss * (NZ + NU + NG) + 255) / 256, blk>>>(
        bi_f, bi_i, bi_o, bi_c, bi_g, bh_f, bh_i, bh_o, bh_g, bh_c,
        biAll, bhfio, bhgc);

    for (int t = 0; t < REPT; t++) {
        // AG[l] = h_cat @ [Wh_g[l]; Wh_c[l]]^T + [bh_g; bh_c]   (batched over l)
        gemm_nt<<<dim3(7, 32, 3), blk>>>(h, SH, 0L,
                                         Whgc, (long)NG * SH, bhgc, NG,
                                         AG, NG, (long)Bsz * NG, NG, SH, 0);
        // U[l] = h_prev[l] @ [Wh_f; Wh_i; Wh_o][l]^T + bias     (batched over l)
        gemm_nt<<<dim3(6, 32, 3), blk>>>(h, SH, (long)Hh,
                                         Whfio, (long)NU * Hh, bhfio, NU,
                                         U, NU, (long)Bsz * NU, NU, Hh, 0);
        for (int l = 0; l < Ss; l++) {
            const float* Ain = (l == 0) ? x : (h + (size_t)(l - 1) * Hh);
            int lda = (l == 0) ? Dd : SH;
            // Z = input_h @ [Wi_f;Wi_i;Wi_o;Wi_c;Wi_g][l]^T + bias
            gemm_nt<<<dim3(9, 32, 1), blk>>>(Ain, lda, 0L,
                                             WiAll + (size_t)l * NZ * Dd, 0L,
                                             biAll + l * NZ, 0,
                                             Z, NZ, 0L, NZ, Dd, 0);
            float* fptr = (l == Ss - 1 && t < REPT - 1) ? (feat + (size_t)t * Hh) : nullptr;
            cell_kernel<<<(Bsz * Hh + 255) / 256, blk>>>(
                Z, U + (size_t)l * Bsz * NU, AG + (size_t)l * Bsz * NG, h, c, fptr, l);
        }
    }

    // out = sigmoid(feat @ W_last^T + b_last)
    gemm_nt<<<dim3(1, 32, 1), blk>>>(feat, FEATK, 0L,
                                     W_last, 0L, b_last, 0,
                                     out, OUTN, 0L, OUTN, FEATK, 1);
}

// round 2
// speedup vs baseline: 2.1290x; 2.1290x over previous
#include <cuda_runtime.h>
#include <cuda_bf16.h>
#include <math.h>

// Problem constants
#define Bsz  4096
#define Dd   256
#define Hh   256
#define Ss   3
#define REPT 10
#define OUTN 44
#define SH   768      // S*H
#define NZ   1027     // concat input-gate rows: f,i,o,c (4*256) + g (3)
#define NU   768      // concat recurrent-gate rows: f,i,o
#define NG   771      // g-logits (3) + aux (768)
#define FEATK 2304    // (REP-1)*H
#define SH2  1536     // split h row: [hi(768) | lo(768)]
#define XW2  512      // split x row: [hi(256) | lo(256)]
#define FEATW2 4608   // split feat row

// ---------------- scratch (static device arrays; no cudaMalloc) ------------
__device__ __nv_bfloat16 g_hsp[(size_t)Bsz * SH2];     // split hidden state
__device__ __nv_bfloat16 g_xsp[(size_t)Bsz * XW2];     // split x
__device__ float         g_c[(size_t)Bsz * SH];        // cell state
__device__ float         g_U[(size_t)Ss * Bsz * NU];
__device__ float         g_AG[(size_t)Ss * Bsz * NG];
__device__ float         g_Z[(size_t)Bsz * NZ];
__device__ __nv_bfloat16 g_featsp[(size_t)Bsz * FEATW2];
__device__ __nv_bfloat16 g_WiAll[(size_t)Ss * NZ * (2*Dd)];
__device__ float         g_biAll[Ss * NZ];
__device__ __nv_bfloat16 g_Whfio[(size_t)Ss * NU * (2*Hh)];
__device__ float         g_bhfio[Ss * NU];
__device__ __nv_bfloat16 g_Whgc[(size_t)Ss * NG * (2*SH)];
__device__ float         g_bhgc[Ss * NG];
__device__ __nv_bfloat16 g_Wlast[(size_t)OUTN * (2*FEATK)];

__device__ __forceinline__ float sigf(float x) { return 1.0f / (1.0f + expf(-x)); }

__device__ __forceinline__ void split_bf16(float v, __nv_bfloat16& hi, __nv_bfloat16& lo) {
    hi = __float2bfloat16(v);
    lo = __float2bfloat16(v - __bfloat162float(hi));
}

// ---------------- bf16 tensor-core GEMM:  C = A' @ W'^T + bias -------------
// Split-K3 trick: logical A row = [Ah(K) | Al(K) | Ah(K)], W row = [Wh|Wh|Wl].
// A storage: hi at +0, lo at +loOff (row stride lda). W storage: [N][2K],
// hi at +0, lo at +K. fp32 accumulate via mma.sync m16n8k16 bf16.
#define BM 128
#define BN 128
#define BK 32
#define SAS 40     // smem row stride (elements) -> 80B, conflict-free ldmatrix

#define LDSM4(r0,r1,r2,r3,addr) \
  asm volatile("ldmatrix.sync.aligned.m8n8.x4.shared.b16 {%0,%1,%2,%3}, [%4];" \
   : "=r"(r0),"=r"(r1),"=r"(r2),"=r"(r3) : "r"(addr))

#define MMA16816(d, a, b) \
  asm volatile("mma.sync.aligned.m16n8k16.row.col.f32.bf16.bf16.f32 " \
    "{%0,%1,%2,%3}, {%4,%5,%6,%7}, {%8,%9}, {%0,%1,%2,%3};" \
    : "+f"(d[0]),"+f"(d[1]),"+f"(d[2]),"+f"(d[3]) \
    : "r"(a[0]),"r"(a[1]),"r"(a[2]),"r"(a[3]), "r"(b[0]),"r"(b[1]))

__global__ void __launch_bounds__(256)
gemm_bf16_nt(const __nv_bfloat16* __restrict__ A, int lda, long sA, int loOff,
             const __nv_bfloat16* __restrict__ W, long sW,
             const float* __restrict__ bias, int sBias,
             float* __restrict__ C, int ldc, long sC,
             int N, int K, int act)
{
    __shared__ __align__(16) __nv_bfloat16 sAm[2][BM * SAS];
    __shared__ __align__(16) __nv_bfloat16 sBm[2][BN * SAS];

    const int z = blockIdx.z;
    A += (size_t)z * sA;
    W += (size_t)z * sW;
    C += (size_t)z * sC;
    const float* bz = bias ? bias + (size_t)z * sBias : nullptr;

    const int m0 = blockIdx.y * BM;
    const int n0 = blockIdx.x * BN;
    const int tid  = threadIdx.x;
    const int warp = tid >> 5;
    const int lane = tid & 31;
    const int wm = warp & 3;    // 4 warp-rows of 32
    const int wn = warp >> 2;   // 2 warp-cols of 64

    const int ktPerSeg = K / BK;
    const int KT = 3 * ktPerSeg;
    const int W2 = 2 * K;

    float acc[2][8][4];
#pragma unroll
    for (int mi = 0; mi < 2; mi++)
#pragma unroll
        for (int ni = 0; ni < 8; ni++)
#pragma unroll
            for (int q = 0; q < 4; q++) acc[mi][ni][q] = 0.f;

    // ---- async loader for one k-tile into stage s ----
    auto load_tiles = [&](int kt, int s) {
        int seg = kt / ktPerSeg;
        int kk  = (kt - seg * ktPerSeg) * BK;
        const __nv_bfloat16* Ap = A + (seg == 1 ? loOff : 0) + kk;
        const __nv_bfloat16* Wp = W + (seg == 2 ? K : 0) + kk;
#pragma unroll
        for (int i = 0; i < 2; i++) {
            int idx = tid + i * 256;
            int row = idx >> 2;
            int ch  = idx & 3;
            unsigned sa = (unsigned)__cvta_generic_to_shared(&sAm[s][row * SAS + ch * 8]);
            const void* ga = Ap + (size_t)(m0 + row) * lda + ch * 8;
            asm volatile("cp.async.cg.shared.global [%0], [%1], 16;" :: "r"(sa), "l"(ga));
            int n = n0 + row;
            int nc = (n < N) ? n : (N - 1);
            unsigned sb = (unsigned)__cvta_generic_to_shared(&sBm[s][row * SAS + ch * 8]);
            const void* gw = Wp + (size_t)nc * W2 + ch * 8;
            int sz = (n < N) ? 16 : 0;
            asm volatile("cp.async.cg.shared.global [%0], [%1], 16, %2;" :: "r"(sb), "l"(gw), "r"(sz));
        }
        asm volatile("cp.async.commit_group;");
    };

    load_tiles(0, 0);
    load_tiles(1, 1);

    const int lt  = lane >> 3;   // ldmatrix tile selector 0..3
    const int lr  = lane & 7;

    for (int kt = 0; kt < KT; kt++) {
        int s = kt & 1;
        asm volatile("cp.async.wait_group 1;");
        __syncthreads();

        const __nv_bfloat16* pa = sAm[s];
        const __nv_bfloat16* pb = sBm[s];
#pragma unroll
        for (int kq = 0; kq < 2; kq++) {
            const int k0 = kq * 16;
            unsigned af[2][4];
#pragma unroll
            for (int mi = 0; mi < 2; mi++) {
                int mrow = wm * 32 + mi * 16 + (lt & 1) * 8 + lr;
                int kcol = k0 + (lt >> 1) * 8;
                unsigned addr = (unsigned)__cvta_generic_to_shared(&pa[mrow * SAS + kcol]);
                LDSM4(af[mi][0], af[mi][1], af[mi][2], af[mi][3], addr);
            }
            unsigned bf[8][2];
#pragma unroll
            for (int nb = 0; nb < 4; nb++) {
                int nrow = wn * 64 + nb * 16 + (lt >> 1) * 8 + lr;
                int kcol = k0 + (lt & 1) * 8;
                unsigned addr = (unsigned)__cvta_generic_to_shared(&pb[nrow * SAS + kcol]);
                unsigned r0, r1, r2, r3;
                LDSM4(r0, r1, r2, r3, addr);
                bf[nb * 2][0] = r0;     bf[nb * 2][1] = r1;
                bf[nb * 2 + 1][0] = r2; bf[nb * 2 + 1][1] = r3;
            }
#pragma unroll
            for (int mi = 0; mi < 2; mi++)
#pragma unroll
                for (int ni = 0; ni < 8; ni++)
                    MMA16816(acc[mi][ni], af[mi], bf[ni]);
        }
        __syncthreads();
        if (kt + 2 < KT) load_tiles(kt + 2, s);
        else asm volatile("cp.async.commit_group;");
    }

    // ---- epilogue ----
#pragma unroll
    for (int mi = 0; mi < 2; mi++) {
        const int r0 = m0 + wm * 32 + mi * 16 + (lane >> 2);
#pragma unroll
        for (int ni = 0; ni < 8; ni++) {
            const int cc = n0 + wn * 64 + ni * 8 + (lane & 3) * 2;
            const float* a = acc[mi][ni];
            if (cc < N) {
                float bv = bz ? bz[cc] : 0.f;
                float v0 = a[0] + bv, v2 = a[2] + bv;
                if (act) { v0 = sigf(v0); v2 = sigf(v2); }
                C[(size_t)r0 * ldc + cc] = v0;
                C[(size_t)(r0 + 8) * ldc + cc] = v2;
            }
            if (cc + 1 < N) {
                float bv = bz ? bz[cc + 1] : 0.f;
                float v1 = a[1] + bv, v3 = a[3] + bv;
                if (act) { v1 = sigf(v1); v3 = sigf(v3); }
                C[(size_t)r0 * ldc + cc + 1] = v1;
                C[(size_t)(r0 + 8) * ldc + cc + 1] = v3;
            }
        }
    }
}

// ---------------- state init: [S,B,H] -> split h + fp32 c ------------------
__global__ void init_state(const float* __restrict__ hid, const float* __restrict__ cur,
                           __nv_bfloat16* __restrict__ hsp, float* __restrict__ c)
{
    int i = blockIdx.x * blockDim.x + threadIdx.x;
    const int total = Ss * Bsz * Hh;
    if (i >= total) return;
    int l = i / (Bsz * Hh);
    int r = i - l * (Bsz * Hh);
    int b = r >> 8;
    int j = r & 255;
    __nv_bfloat16 hi, lo;
    split_bf16(hid[i], hi, lo);
    hsp[(size_t)b * SH2 + l * Hh + j] = hi;
    hsp[(size_t)b * SH2 + SH + l * Hh + j] = lo;
    c[(size_t)b * SH + l * Hh + j] = cur[i];
}

__global__ void split_x(const float* __restrict__ x, __nv_bfloat16* __restrict__ xsp)
{
    int i = blockIdx.x * blockDim.x + threadIdx.x;
    if (i >= Bsz * Dd) return;
    int b = i >> 8, j = i & 255;
    __nv_bfloat16 hi, lo;
    split_bf16(x[i], hi, lo);
    xsp[(size_t)b * XW2 + j] = hi;
    xsp[(size_t)b * XW2 + Dd + j] = lo;
}

// ---------------- weight repacks (fp32 -> split bf16, concat rows) ---------
__global__ void repack_wi(const float* __restrict__ wf, const float* __restrict__ wi,
                          const float* __restrict__ wo, const float* __restrict__ wc,
                          const float* __restrict__ wg, __nv_bfloat16* __restrict__ out)
{
    int idx = blockIdx.x * blockDim.x + threadIdx.x;
    if (idx >= Ss * NZ * Dd) return;
    int k = idx % Dd;
    int r = (idx / Dd) % NZ;
    int l = idx / (Dd * NZ);
    float v;
    if      (r < 256)  v = wf[((size_t)l * Hh + r)        * Dd + k];
    else if (r < 512)  v = wi[((size_t)l * Hh + r - 256)  * Dd + k];
    else if (r < 768)  v = wo[((size_t)l * Hh + r - 512)  * Dd + k];
    else if (r < 1024) v = wc[((size_t)l * Hh + r - 768)  * Dd + k];
    else               v = wg[((size_t)l * Ss + r - 1024) * Dd + k];
    __nv_bfloat16 hi, lo;
    split_bf16(v, hi, lo);
    size_t o = ((size_t)l * NZ + r) * (2 * Dd) + k;
    out[o] = hi;
    out[o + Dd] = lo;
}

__global__ void repack_whfio(const float* __restrict__ wf, const float* __restrict__ wi,
                             const float* __restrict__ wo, __nv_bfloat16* __restrict__ out)
{
    int idx = blockIdx.x * blockDim.x + threadIdx.x;
    if (idx >= Ss * NU * Hh) return;
    int k = idx % Hh;
    int r = (idx / Hh) % NU;
    int l = idx / (Hh * NU);
    float v;
    if      (r < 256) v = wf[((size_t)l * Hh + r)       * Hh + k];
    else if (r < 512) v = wi[((size_t)l * Hh + r - 256) * Hh + k];
    else              v = wo[((size_t)l * Hh + r - 512) * Hh + k];
    __nv_bfloat16 hi, lo;
    split_bf16(v, hi, lo);
    size_t o = ((size_t)l * NU + r) * (2 * Hh) + k;
    out[o] = hi;
    out[o + Hh] = lo;
}

__global__ void repack_whgc(const float* __restrict__ wg, const float* __restrict__ wc,
                            __nv_bfloat16* __restrict__ out)
{
    int idx = blockIdx.x * blockDim.x + threadIdx.x;
    if (idx >= Ss * NG * SH) return;
    int k = idx % SH;
    int r = (idx / SH) % NG;
    int l = idx / (SH * NG);
    float v;
    if (r < 3) v = wg[((size_t)l * Ss + r)     * SH + k];
    else       v = wc[((size_t)l * SH + r - 3) * SH + k];
    __nv_bfloat16 hi, lo;
    split_bf16(v, hi, lo);
    size_t o = ((size_t)l * NG + r) * (2 * SH) + k;
    out[o] = hi;
    out[o + SH] = lo;
}

__global__ void repack_wlast(const float* __restrict__ w, __nv_bfloat16* __restrict__ out)
{
    int idx = blockIdx.x * blockDim.x + threadIdx.x;
    if (idx >= OUTN * FEATK) return;
    int k = idx % FEATK;
    int r = idx / FEATK;
    __nv_bfloat16 hi, lo;
    split_bf16(w[idx], hi, lo);
    size_t o = (size_t)r * (2 * FEATK) + k;
    out[o] = hi;
    out[o + FEATK] = lo;
}

__global__ void repack_bias(const float* __restrict__ bif, const float* __restrict__ bii,
                            const float* __restrict__ bio, const float* __restrict__ bic,
                            const float* __restrict__ big,
                            const float* __restrict__ bhf, const float* __restrict__ bhi,
                            const float* __restrict__ bho, const float* __restrict__ bhg,
                            const float* __restrict__ bhc,
                            float* __restrict__ biAll, float* __restrict__ bhfio,
                            float* __restrict__ bhgc)
{
    int idx = blockIdx.x * blockDim.x + threadIdx.x;
    const int n1 = Ss * NZ;
    const int n2 = n1 + Ss * NU;
    const int n3 = n2 + Ss * NG;
    if (idx < n1) {
        int r = idx % NZ, l = idx / NZ;
        float v;
        if      (r < 256)  v = bif[l * Hh + r];
        else if (r < 512)  v = bii[l * Hh + r - 256];
        else if (r < 768)  v = bio[l * Hh + r - 512];
        else if (r < 1024) v = bic[l * Hh + r - 768];
        else               v = big[l * Ss + r - 1024];
        biAll[idx] = v;
    } else if (idx < n2) {
        int t = idx - n1;
        int r = t % NU, l = t / NU;
        float v;
        if      (r < 256) v = bhf[l * Hh + r];
        else if (r < 512) v = bhi[l * Hh + r - 256];
        else              v = bho[l * Hh + r - 512];
        bhfio[t] = v;
    } else if (idx < n3) {
        int t = idx - n2;
        int r = t % NG, l = t / NG;
        bhgc[t] = (r < 3) ? bhg[l * Ss + r] : bhc[l * SH + r - 3];
    }
}

// ---------------- per-layer LSTM cell --------------------------------------
__global__ void cell_kernel(const float* __restrict__ Z, const float* __restrict__ U,
                            const float* __restrict__ AG,
                            __nv_bfloat16* __restrict__ hsp, float* __restrict__ c,
                            __nv_bfloat16* __restrict__ featsp, int l, int t)
{
    int idx = blockIdx.x * blockDim.x + threadIdx.x;
    if (idx >= Bsz * Hh) return;
    int b = idx >> 8;
    int j = idx & 255;
    const float* Zb = Z + (size_t)b * NZ;
    const float* Ub = U + (size_t)b * NU;
    const float* Gb = AG + (size_t)b * NG;

    float g0 = sigf(Zb[1024] + Gb[0]);
    float g1 = sigf(Zb[1025] + Gb[1]);
    float g2 = sigf(Zb[1026] + Gb[2]);
    float aux = g0 * Gb[3 + j] + g1 * Gb[3 + 256 + j] + g2 * Gb[3 + 512 + j];

    float fg = sigf(Zb[j]       + Ub[j]);
    float ig = sigf(Zb[256 + j] + Ub[256 + j]);
    float og = sigf(Zb[512 + j] + Ub[512 + j]);
    float ct = tanhf(Zb[768 + j] + aux);

    size_t sidx = (size_t)b * SH + l * Hh + j;
    float cn = fg * c[sidx] + ig * ct;
    float hn = og * cn;
    c[sidx] = cn;

    __nv_bfloat16 hh, hl;
    split_bf16(hn, hh, hl);
    hsp[(size_t)b * SH2 + l * Hh + j] = hh;
    hsp[(size_t)b * SH2 + SH + l * Hh + j] = hl;
    if (featsp) {
        featsp[(size_t)b * FEATW2 + t * Hh + j] = hh;
        featsp[(size_t)b * FEATW2 + FEATK + t * Hh + j] = hl;
    }
}

// ---------------- orchestration --------------------------------------------
extern "C" void kernel_launch(void* const* d_in, const int* in_sizes, int n_in,
                              void* d_out, int out_size)
{
    (void)in_sizes; (void)n_in; (void)out_size;
    const float* x    = (const float*)d_in[0];
    const float* hid0 = (const float*)d_in[1];
    const float* cur0 = (const float*)d_in[2];
    const float* Wi_f = (const float*)d_in[3];
    const float* bi_f = (const float*)d_in[4];
    const float* Wi_i = (const float*)d_in[5];
    const float* bi_i = (const float*)d_in[6];
    const float* Wi_o = (const float*)d_in[7];
    const float* bi_o = (const float*)d_in[8];
    const float* Wi_c = (const float*)d_in[9];
    const float* bi_c = (const float*)d_in[10];
    const float* Wi_g = (const float*)d_in[11];
    const float* bi_g = (const float*)d_in[12];
    const float* Wh_f = (const float*)d_in[13];
    const float* bh_f = (const float*)d_in[14];
    const float* Wh_i = (const float*)d_in[15];
    const float* bh_i = (const float*)d_in[16];
    const float* Wh_o = (const float*)d_in[17];
    const float* bh_o = (const float*)d_in[18];
    const float* Wh_g = (const float*)d_in[19];
    const float* bh_g = (const float*)d_in[20];
    const float* Wh_c = (const float*)d_in[21];
    const float* bh_c = (const float*)d_in[22];
    const float* W_last = (const float*)d_in[23];
    const float* b_last = (const float*)d_in[24];
    float* out = (float*)d_out;

    __nv_bfloat16 *hsp, *xsp, *featsp, *WiAll, *Whfio, *Whgc, *Wlast;
    float *c, *U, *AG, *Z, *biAll, *bhfio, *bhgc;
    cudaGetSymbolAddress((void**)&hsp,    g_hsp);
    cudaGetSymbolAddress((void**)&xsp,    g_xsp);
    cudaGetSymbolAddress((void**)&featsp, g_featsp);
    cudaGetSymbolAddress((void**)&c,      g_c);
    cudaGetSymbolAddress((void**)&U,      g_U);
    cudaGetSymbolAddress((void**)&AG,     g_AG);
    cudaGetSymbolAddress((void**)&Z,      g_Z);
    cudaGetSymbolAddress((void**)&WiAll,  g_WiAll);
    cudaGetSymbolAddress((void**)&biAll,  g_biAll);
    cudaGetSymbolAddress((void**)&Whfio,  g_Whfio);
    cudaGetSymbolAddress((void**)&bhfio,  g_bhfio);
    cudaGetSymbolAddress((void**)&Whgc,   g_Whgc);
    cudaGetSymbolAddress((void**)&bhgc,   g_bhgc);
    cudaGetSymbolAddress((void**)&Wlast,  g_Wlast);

    const dim3 blk(256);

    init_state<<<(Ss * Bsz * Hh + 255) / 256, blk>>>(hid0, cur0, hsp, c);
    split_x<<<(Bsz * Dd + 255) / 256, blk>>>(x, xsp);
    repack_wi<<<(Ss * NZ * Dd + 255) / 256, blk>>>(Wi_f, Wi_i, Wi_o, Wi_c, Wi_g, WiAll);
    repack_whfio<<<(Ss * NU * Hh + 255) / 256, blk>>>(Wh_f, Wh_i, Wh_o, Whfio);
    repack_whgc<<<(Ss * NG * SH + 255) / 256, blk>>>(Wh_g, Wh_c, Whgc);
    repack_wlast<<<(OUTN * FEATK + 255) / 256, blk>>>(W_last, Wlast);
    repack_bias<<<(Ss * (NZ + NU + NG) + 255) / 256, blk>>>(
        bi_f, bi_i, bi_o, bi_c, bi_g, bh_f, bh_i, bh_o, bh_g, bh_c,
        biAll, bhfio, bhgc);

    for (int t = 0; t < REPT; t++) {
        // AG[l] = h_cat @ [Wh_g[l]; Wh_c[l]]^T + bias   (batched over l)
        gemm_bf16_nt<<<dim3(7, 32, 3), blk>>>(hsp, SH2, 0L, SH,
                                              Whgc, (long)NG * (2 * SH),
                                              bhgc, NG,
                                              AG, NG, (long)Bsz * NG, NG, SH, 0);
        // U[l] = h_prev[l] @ [Wh_f;Wh_i;Wh_o][l]^T + bias  (batched over l)
        gemm_bf16_nt<<<dim3(6, 32, 3), blk>>>(hsp, SH2, (long)Hh, SH,
                                              Whfio, (long)NU * (2 * Hh),
                                              bhfio, NU,
                                              U, NU, (long)Bsz * NU, NU, Hh, 0);
        for (int l = 0; l < Ss; l++) {
            const __nv_bfloat16* Ain = (l == 0) ? xsp : (hsp + (size_t)(l - 1) * Hh);
            int lda   = (l == 0) ? XW2 : SH2;
            int loOff = (l == 0) ? Dd  : SH;
            gemm_bf16_nt<<<dim3(9, 32, 1), blk>>>(Ain, lda, 0L, loOff,
                                                  WiAll + (size_t)l * NZ * (2 * Dd), 0L,
                                                  biAll + l * NZ, 0,
                                                  Z, NZ, 0L, NZ, Dd, 0);
            __nv_bfloat16* fptr = (l == Ss - 1 && t < REPT - 1) ? featsp : nullptr;
            cell_kernel<<<(Bsz * Hh + 255) / 256, blk>>>(
                Z, U + (size_t)l * Bsz * NU, AG + (size_t)l * Bsz * NG,
                hsp, c, fptr, l, t);
        }
    }

    // out = sigmoid(feat @ W_last^T + b_last)
    gemm_bf16_nt<<<dim3(1, 32, 1), blk>>>(featsp, FEATW2, 0L, FEATK,
                                          Wlast, 0L, b_last, 0,
                                          out, OUTN, 0L, OUTN, FEATK, 1);
}

// round 4
// speedup vs baseline: 2.8079x; 1.3189x over previous
#include <cuda_runtime.h>
#include <cuda_bf16.h>
#include <math.h>
#include <stdint.h>

// Problem constants
#define Bsz  4096
#define Dd   256
#define Hh   256
#define Ss   3
#define REPT 10
#define OUTN 44
#define SH   768      // S*H
#define NZ   1027     // concat input-gate rows: f,i,o,c (4*256) + g (3)
#define ZLD  1028     // padded ldc for Z
#define NU   768
#define NAG  2304     // slim fused AG: 3 layers x 768 aux rows
#define FEATK 2304    // (REP-1)*H
#define SH2  1536     // split h row: [hi(768) | lo(768)]
#define XW2  512      // split x row: [hi(256) | lo(256)]
#define FEATW2 4608   // split feat row

// ---------------- scratch (static device arrays; no cudaMalloc) ------------
__device__ __nv_bfloat16 g_hsp[(size_t)Bsz * SH2];
__device__ float         g_hf[(size_t)Bsz * SH];     // fp32 h_cat copy
__device__ __nv_bfloat16 g_xsp[(size_t)Bsz * XW2];
__device__ float         g_c[(size_t)Bsz * SH];
__device__ float         g_U[(size_t)Ss * Bsz * NU];
__device__ float         g_AG[(size_t)Bsz * NAG];
__device__ float         g_G2[(size_t)Bsz * 12];     // Wh_g . h_cat + bh_g, 9 used
__device__ float         g_Z[(size_t)Bsz * ZLD];
__device__ float         g_Z0[(size_t)Bsz * ZLD];
__device__ __nv_bfloat16 g_featsp[(size_t)Bsz * FEATW2];
__device__ __nv_bfloat16 g_WiAll[(size_t)Ss * NZ * (2*Dd)];
__device__ float         g_biAll[Ss * NZ];
__device__ __nv_bfloat16 g_Whfio[(size_t)Ss * NU * (2*Hh)];
__device__ float         g_bhfio[Ss * NU];
__device__ __nv_bfloat16 g_Whc[(size_t)NAG * (2*SH)];   // slim fused, split
__device__ float         g_bhcAll[NAG];
__device__ __nv_bfloat16 g_Wlast[(size_t)OUTN * (2*FEATK)];

__device__ __forceinline__ float sigf(float x) { return 1.0f / (1.0f + expf(-x)); }

__device__ __forceinline__ void split_bf16(float v, __nv_bfloat16& hi, __nv_bfloat16& lo) {
    hi = __float2bfloat16(v);
    lo = __float2bfloat16(v - __bfloat162float(hi));
}

// ---------------- bf16 HMMA GEMM:  C = A' @ W'^T + bias --------------------
// Split-K3: logical A row = [Ah(K) | Al(K) | Ah(K)], W row = [Wh|Wh|Wl].
// A: hi at +0, lo at +loOff (row stride lda). W: [N][2K], hi|lo.
// 3-stage cp.async pipeline, 128x128x32 tiles, mma.sync m16n8k16 bf16.
#define BM 128
#define BN 128
#define BK 32
#define SAS 40                    // smem row stride (elems) -> 80B, conflict-free
#define STG_E (BM * SAS)          // 5120 elems per tile
#define SMEM_GEMM (3 * 2 * STG_E * 2)   // 3 stages x (A+B) x bf16 = 61440 B

#define LDSM4(r0,r1,r2,r3,addr) \
  asm volatile("ldmatrix.sync.aligned.m8n8.x4.shared.b16 {%0,%1,%2,%3}, [%4];" \
   : "=r"(r0),"=r"(r1),"=r"(r2),"=r"(r3) : "r"(addr))

#define MMA16816(d, a, b) \
  asm volatile("mma.sync.aligned.m16n8k16.row.col.f32.bf16.bf16.f32 " \
    "{%0,%1,%2,%3}, {%4,%5,%6,%7}, {%8,%9}, {%0,%1,%2,%3};" \
    : "+f"(d[0]),"+f"(d[1]),"+f"(d[2]),"+f"(d[3]) \
    : "r"(a[0]),"r"(a[1]),"r"(a[2]),"r"(a[3]), "r"(b[0]),"r"(b[1]))

__global__ void __launch_bounds__(256, 2)
gemm_bf16_nt(const __nv_bfloat16* __restrict__ A, int lda, long sA, int loOff,
             const __nv_bfloat16* __restrict__ W, long sW,
             const float* __restrict__ bias, int sBias,
             float* __restrict__ C, int ldc, long sC,
             int N, int K, int act)
{
    extern __shared__ __align__(16) __nv_bfloat16 smem[];
    // stage s: A at smem + s*2*STG_E, B at +STG_E

    const int z = blockIdx.z;
    A += (size_t)z * sA;
    W += (size_t)z * sW;
    C += (size_t)z * sC;
    const float* bz = bias ? bias + (size_t)z * sBias : nullptr;

    const int m0 = blockIdx.y * BM;
    const int n0 = blockIdx.x * BN;
    const int tid  = threadIdx.x;
    const int warp = tid >> 5;
    const int lane = tid & 31;
    const int wm = warp & 3;    // 4 warp-rows of 32
    const int wn = warp >> 2;   // 2 warp-cols of 64

    const int ktPerSeg = K / BK;
    const int KT = 3 * ktPerSeg;
    const int W2 = 2 * K;

    float acc[2][8][4];
#pragma unroll
    for (int mi = 0; mi < 2; mi++)
#pragma unroll
        for (int ni = 0; ni < 8; ni++)
#pragma unroll
            for (int q = 0; q < 4; q++) acc[mi][ni][q] = 0.f;

    auto load_tiles = [&](int kt, int s) {
        int seg = kt / ktPerSeg;
        int kk  = (kt - seg * ktPerSeg) * BK;
        const __nv_bfloat16* Ap = A + (seg == 1 ? loOff : 0) + kk;
        const __nv_bfloat16* Wp = W + (seg == 2 ? K : 0) + kk;
        __nv_bfloat16* sa0 = smem + s * 2 * STG_E;
        __nv_bfloat16* sb0 = sa0 + STG_E;
#pragma unroll
        for (int i = 0; i < 2; i++) {
            int idx = tid + i * 256;
            int row = idx >> 2;
            int ch  = idx & 3;
            unsigned sa = (unsigned)__cvta_generic_to_shared(&sa0[row * SAS + ch * 8]);
            const void* ga = Ap + (size_t)(m0 + row) * lda + ch * 8;
            asm volatile("cp.async.cg.shared.global [%0], [%1], 16;" :: "r"(sa), "l"(ga));
            int n = n0 + row;
            int nc = (n < N) ? n : (N - 1);
            unsigned sb = (unsigned)__cvta_generic_to_shared(&sb0[row * SAS + ch * 8]);
            const void* gw = Wp + (size_t)nc * W2 + ch * 8;
            int sz = (n < N) ? 16 : 0;
            asm volatile("cp.async.cg.shared.global [%0], [%1], 16, %2;" :: "r"(sb), "l"(gw), "r"(sz));
        }
        asm volatile("cp.async.commit_group;");
    };

    load_tiles(0, 0);
    load_tiles(1, 1);

    const int lt  = lane >> 3;
    const int lr  = lane & 7;

    int s = 0;
    for (int kt = 0; kt < KT; kt++) {
        asm volatile("cp.async.wait_group 1;");
        __syncthreads();

        const __nv_bfloat16* pa = smem + s * 2 * STG_E;
        const __nv_bfloat16* pb = pa + STG_E;
#pragma unroll
        for (int kq = 0; kq < 2; kq++) {
            const int k0 = kq * 16;
            unsigned af[2][4];
#pragma unroll
            for (int mi = 0; mi < 2; mi++) {
                int mrow = wm * 32 + mi * 16 + (lt & 1) * 8 + lr;
                int kcol = k0 + (lt >> 1) * 8;
                unsigned addr = (unsigned)__cvta_generic_to_shared(&pa[mrow * SAS + kcol]);
                LDSM4(af[mi][0], af[mi][1], af[mi][2], af[mi][3], addr);
            }
            unsigned bf[8][2];
#pragma unroll
            for (int nb = 0; nb < 4; nb++) {
                int nrow = wn * 64 + nb * 16 + (lt >> 1) * 8 + lr;
                int kcol = k0 + (lt & 1) * 8;
                unsigned addr = (unsigned)__cvta_generic_to_shared(&pb[nrow * SAS + kcol]);
                unsigned r0, r1, r2, r3;
                LDSM4(r0, r1, r2, r3, addr);
                bf[nb * 2][0] = r0;     bf[nb * 2][1] = r1;
                bf[nb * 2 + 1][0] = r2; bf[nb * 2 + 1][1] = r3;
            }
#pragma unroll
            for (int mi = 0; mi < 2; mi++)
#pragma unroll
                for (int ni = 0; ni < 8; ni++)
                    MMA16816(acc[mi][ni], af[mi], bf[ni]);
        }
        // stage (kt+2)%3 last held tile kt-1; all warps passed this iter's
        // top barrier only after finishing tile kt-1 -> safe to overwrite.
        if (kt + 2 < KT) load_tiles(kt + 2, (s + 2 >= 3) ? s - 1 : s + 2);
        else asm volatile("cp.async.commit_group;");
        if (++s == 3) s = 0;
    }

    // ---- epilogue ----
#pragma unroll
    for (int mi = 0; mi < 2; mi++) {
        const int r0 = m0 + wm * 32 + mi * 16 + (lane >> 2);
#pragma unroll
        for (int ni = 0; ni < 8; ni++) {
            const int cc = n0 + wn * 64 + ni * 8 + (lane & 3) * 2;
            const float* a = acc[mi][ni];
            if (cc < N) {
                float bv = bz ? bz[cc] : 0.f;
                float v0 = a[0] + bv, v2 = a[2] + bv;
                if (act) { v0 = sigf(v0); v2 = sigf(v2); }
                C[(size_t)r0 * ldc + cc] = v0;
                C[(size_t)(r0 + 8) * ldc + cc] = v2;
            }
            if (cc + 1 < N) {
                float bv = bz ? bz[cc + 1] : 0.f;
                float v1 = a[1] + bv, v3 = a[3] + bv;
                if (act) { v1 = sigf(v1); v3 = sigf(v3); }
                C[(size_t)r0 * ldc + cc + 1] = v1;
                C[(size_t)(r0 + 8) * ldc + cc + 1] = v3;
            }
        }
    }
}

// ---------------- g-logit part2: G2[b][o] = Wh_g[o] . h_cat[b] + bh_g ------
__global__ void glog2_kernel(const float* __restrict__ hf,
                             const float* __restrict__ whg,   // [9][768] = Wh_g
                             const float* __restrict__ bhg,   // [9]
                             float* __restrict__ G2)
{
    int gw = (blockIdx.x * blockDim.x + threadIdx.x) >> 5;
    int lane = threadIdx.x & 31;
    if (gw >= Bsz * 9) return;
    int b = gw / 9;
    int o = gw - b * 9;
    const float* hr = hf + (size_t)b * SH;
    const float* wr = whg + (size_t)o * SH;
    float sum = 0.f;
#pragma unroll 6
    for (int k = lane; k < SH; k += 32) sum += hr[k] * wr[k];
#pragma unroll
    for (int off = 16; off; off >>= 1) sum += __shfl_xor_sync(0xFFFFFFFFu, sum, off);
    if (lane == 0) G2[(size_t)b * 12 + o] = sum + bhg[o];
}

// ---------------- state init / splits --------------------------------------
__global__ void init_state(const float* __restrict__ hid, const float* __restrict__ cur,
                           __nv_bfloat16* __restrict__ hsp, float* __restrict__ hf,
                           float* __restrict__ c)
{
    int i = blockIdx.x * blockDim.x + threadIdx.x;
    const int total = Ss * Bsz * Hh;
    if (i >= total) return;
    int l = i / (Bsz * Hh);
    int r = i - l * (Bsz * Hh);
    int b = r >> 8;
    int j = r & 255;
    __nv_bfloat16 hi, lo;
    float v = hid[i];
    split_bf16(v, hi, lo);
    hsp[(size_t)b * SH2 + l * Hh + j] = hi;
    hsp[(size_t)b * SH2 + SH + l * Hh + j] = lo;
    hf[(size_t)b * SH + l * Hh + j] = v;
    c[(size_t)b * SH + l * Hh + j] = cur[i];
}

__global__ void split_x(const float* __restrict__ x, __nv_bfloat16* __restrict__ xsp)
{
    int i = blockIdx.x * blockDim.x + threadIdx.x;
    if (i >= Bsz * Dd) return;
    int b = i >> 8, j = i & 255;
    __nv_bfloat16 hi, lo;
    split_bf16(x[i], hi, lo);
    xsp[(size_t)b * XW2 + j] = hi;
    xsp[(size_t)b * XW2 + Dd + j] = lo;
}

// ---------------- weight repacks (fp32 -> split bf16, concat rows) ---------
__global__ void repack_wi(const float* __restrict__ wf, const float* __restrict__ wi,
                          const float* __restrict__ wo, const float* __restrict__ wc,
                          const float* __restrict__ wg, __nv_bfloat16* __restrict__ out)
{
    int idx = blockIdx.x * blockDim.x + threadIdx.x;
    if (idx >= Ss * NZ * Dd) return;
    int k = idx % Dd;
    int r = (idx / Dd) % NZ;
    int l = idx / (Dd * NZ);
    float v;
    if      (r < 256)  v = wf[((size_t)l * Hh + r)        * Dd + k];
    else if (r < 512)  v = wi[((size_t)l * Hh + r - 256)  * Dd + k];
    else if (r < 768)  v = wo[((size_t)l * Hh + r - 512)  * Dd + k];
    else if (r < 1024) v = wc[((size_t)l * Hh + r - 768)  * Dd + k];
    else               v = wg[((size_t)l * Ss + r - 1024) * Dd + k];
    __nv_bfloat16 hi, lo;
    split_bf16(v, hi, lo);
    size_t o = ((size_t)l * NZ + r) * (2 * Dd) + k;
    out[o] = hi;
    out[o + Dd] = lo;
}

__global__ void repack_whfio(const float* __restrict__ wf, const float* __restrict__ wi,
                             const float* __restrict__ wo, __nv_bfloat16* __restrict__ out)
{
    int idx = blockIdx.x * blockDim.x + threadIdx.x;
    if (idx >= Ss * NU * Hh) return;
    int k = idx % Hh;
    int r = (idx / Hh) % NU;
    int l = idx / (Hh * NU);
    float v;
    if      (r < 256) v = wf[((size_t)l * Hh + r)       * Hh + k];
    else if (r < 512) v = wi[((size_t)l * Hh + r - 256) * Hh + k];
    else              v = wo[((size_t)l * Hh + r - 512) * Hh + k];
    __nv_bfloat16 hi, lo;
    split_bf16(v, hi, lo);
    size_t o = ((size_t)l * NU + r) * (2 * Hh) + k;
    out[o] = hi;
    out[o + Hh] = lo;
}

// slim fused Wh_c: out row r = l*768+q  <-  Wh_c[l][q][:], split
__global__ void repack_whc(const float* __restrict__ wc, __nv_bfloat16* __restrict__ out)
{
    int idx = blockIdx.x * blockDim.x + threadIdx.x;
    if (idx >= NAG * SH) return;
    int k = idx % SH;
    int r = idx / SH;
    float v = wc[(size_t)r * SH + k];   // Wh_c is [3][768][768] contiguous == [2304][768]
    __nv_bfloat16 hi, lo;
    split_bf16(v, hi, lo);
    size_t o = (size_t)r * (2 * SH) + k;
    out[o] = hi;
    out[o + SH] = lo;
}

__global__ void repack_wlast(const float* __restrict__ w, __nv_bfloat16* __restrict__ out)
{
    int idx = blockIdx.x * blockDim.x + threadIdx.x;
    if (idx >= OUTN * FEATK) return;
    int k = idx % FEATK;
    int r = idx / FEATK;
    __nv_bfloat16 hi, lo;
    split_bf16(w[idx], hi, lo);
    size_t o = (size_t)r * (2 * FEATK) + k;
    out[o] = hi;
    out[o + FEATK] = lo;
}

__global__ void repack_bias(const float* __restrict__ bif, const float* __restrict__ bii,
                            const float* __restrict__ bio, const float* __restrict__ bic,
                            const float* __restrict__ big,
                            const float* __restrict__ bhf, const float* __restrict__ bhi,
                            const float* __restrict__ bho,
                            const float* __restrict__ bhc,
                            float* __restrict__ biAll, float* __restrict__ bhfio,
                            float* __restrict__ bhcAll)
{
    int idx = blockIdx.x * blockDim.x + threadIdx.x;
    const int n1 = Ss * NZ;
    const int n2 = n1 + Ss * NU;
    const int n3 = n2 + NAG;
    if (idx < n1) {
        int r = idx % NZ, l = idx / NZ;
        float v;
        if      (r < 256)  v = bif[l * Hh + r];
        else if (r < 512)  v = bii[l * Hh + r - 256];
        else if (r < 768)  v = bio[l * Hh + r - 512];
        else if (r < 1024) v = bic[l * Hh + r - 768];
        else               v = big[l * Ss + r - 1024];
        biAll[idx] = v;
    } else if (idx < n2) {
        int t = idx - n1;
        int r = t % NU, l = t / NU;
        float v;
        if      (r < 256) v = bhf[l * Hh + r];
        else if (r < 512) v = bhi[l * Hh + r - 256];
        else              v = bho[l * Hh + r - 512];
        bhfio[t] = v;
    } else if (idx < n3) {
        int t = idx - n2;
        bhcAll[t] = bhc[t];   // bh_c is [3][768] contiguous == [2304]
    }
}

// ---------------- per-layer LSTM cell --------------------------------------
__global__ void cell_kernel(const float* __restrict__ Z, const float* __restrict__ U,
                            const float* __restrict__ AG, const float* __restrict__ G2,
                            __nv_bfloat16* __restrict__ hsp, float* __restrict__ hf,
                            float* __restrict__ c,
                            __nv_bfloat16* __restrict__ featsp, int l, int t)
{
    int idx = blockIdx.x * blockDim.x + threadIdx.x;
    if (idx >= Bsz * Hh) return;
    int b = idx >> 8;
    int j = idx & 255;
    const float* Zb = Z + (size_t)b * ZLD;
    const float* Ub = U + (size_t)b * NU;
    const float* Gb = AG + (size_t)b * NAG + l * SH;
    const float* g2 = G2 + (size_t)b * 12 + l * 3;

    float g0 = sigf(Zb[1024] + g2[0]);
    float g1 = sigf(Zb[1025] + g2[1]);
    float g2v = sigf(Zb[1026] + g2[2]);
    float aux = g0 * Gb[j] + g1 * Gb[256 + j] + g2v * Gb[512 + j];

    float fg = sigf(Zb[j]       + Ub[j]);
    float ig = sigf(Zb[256 + j] + Ub[256 + j]);
    float og = sigf(Zb[512 + j] + Ub[512 + j]);
    float ct = tanhf(Zb[768 + j] + aux);

    size_t sidx = (size_t)b * SH + l * Hh + j;
    float cn = fg * c[sidx] + ig * ct;
    float hn = og * cn;
    c[sidx] = cn;
    hf[sidx] = hn;

    __nv_bfloat16 hh, hl;
    split_bf16(hn, hh, hl);
    hsp[(size_t)b * SH2 + l * Hh + j] = hh;
    hsp[(size_t)b * SH2 + SH + l * Hh + j] = hl;
    if (featsp) {
        featsp[(size_t)b * FEATW2 + t * Hh + j] = hh;
        featsp[(size_t)b * FEATW2 + FEATK + t * Hh + j] = hl;
    }
}

// ---------------- orchestration --------------------------------------------
extern "C" void kernel_launch(void* const* d_in, const int* in_sizes, int n_in,
                              void* d_out, int out_size)
{
    (void)in_sizes; (void)n_in; (void)out_size;
    const float* x    = (const float*)d_in[0];
    const float* hid0 = (const float*)d_in[1];
    const float* cur0 = (const float*)d_in[2];
    const float* Wi_f = (const float*)d_in[3];
    const float* bi_f = (const float*)d_in[4];
    const float* Wi_i = (const float*)d_in[5];
    const float* bi_i = (const float*)d_in[6];
    const float* Wi_o = (const float*)d_in[7];
    const float* bi_o = (const float*)d_in[8];
    const float* Wi_c = (const float*)d_in[9];
    const float* bi_c = (const float*)d_in[10];
    const float* Wi_g = (const float*)d_in[11];
    const float* bi_g = (const float*)d_in[12];
    const float* Wh_f = (const float*)d_in[13];
    const float* bh_f = (const float*)d_in[14];
    const float* Wh_i = (const float*)d_in[15];
    const float* bh_i = (const float*)d_in[16];
    const float* Wh_o = (const float*)d_in[17];
    const float* bh_o = (const float*)d_in[18];
    const float* Wh_g = (const float*)d_in[19];
    const float* bh_g = (const float*)d_in[20];
    const float* Wh_c = (const float*)d_in[21];
    const float* bh_c = (const float*)d_in[22];
    const float* W_last = (const float*)d_in[23];
    const float* b_last = (const float*)d_in[24];
    float* out = (float*)d_out;

    __nv_bfloat16 *hsp, *xsp, *featsp, *WiAll, *Whfio, *Whc, *Wlast;
    float *hf, *c, *U, *AG, *G2, *Z, *Z0, *biAll, *bhfio, *bhcAll;
    cudaGetSymbolAddress((void**)&hsp,    g_hsp);
    cudaGetSymbolAddress((void**)&hf,     g_hf);
    cudaGetSymbolAddress((void**)&xsp,    g_xsp);
    cudaGetSymbolAddress((void**)&featsp, g_featsp);
    cudaGetSymbolAddress((void**)&c,      g_c);
    cudaGetSymbolAddress((void**)&U,      g_U);
    cudaGetSymbolAddress((void**)&AG,     g_AG);
    cudaGetSymbolAddress((void**)&G2,     g_G2);
    cudaGetSymbolAddress((void**)&Z,      g_Z);
    cudaGetSymbolAddress((void**)&Z0,     g_Z0);
    cudaGetSymbolAddress((void**)&WiAll,  g_WiAll);
    cudaGetSymbolAddress((void**)&biAll,  g_biAll);
    cudaGetSymbolAddress((void**)&Whfio,  g_Whfio);
    cudaGetSymbolAddress((void**)&bhfio,  g_bhfio);
    cudaGetSymbolAddress((void**)&Whc,    g_Whc);
    cudaGetSymbolAddress((void**)&bhcAll, g_bhcAll);
    cudaGetSymbolAddress((void**)&Wlast,  g_Wlast);

    cudaFuncSetAttribute(gemm_bf16_nt, cudaFuncAttributeMaxDynamicSharedMemorySize, SMEM_GEMM);

    const dim3 blk(256);

    init_state<<<(Ss * Bsz * Hh + 255) / 256, blk>>>(hid0, cur0, hsp, hf, c);
    split_x<<<(Bsz * Dd + 255) / 256, blk>>>(x, xsp);
    repack_wi<<<(Ss * NZ * Dd + 255) / 256, blk>>>(Wi_f, Wi_i, Wi_o, Wi_c, Wi_g, WiAll);
    repack_whfio<<<(Ss * NU * Hh + 255) / 256, blk>>>(Wh_f, Wh_i, Wh_o, Whfio);
    repack_whc<<<(NAG * SH + 255) / 256, blk>>>(Wh_c, Whc);
    repack_wlast<<<(OUTN * FEATK + 255) / 256, blk>>>(W_last, Wlast);
    repack_bias<<<(Ss * (NZ + NU) + NAG + 255) / 256, blk>>>(
        bi_f, bi_i, bi_o, bi_c, bi_g, bh_f, bh_i, bh_o, bh_c,
        biAll, bhfio, bhcAll);

    // Z0 = x @ Wi[0]^T + bias : time-invariant, hoisted out of the loop
    gemm_bf16_nt<<<dim3(9, 32, 1), blk, SMEM_GEMM>>>(xsp, XW2, 0L, Dd,
                                                     WiAll, 0L, biAll, 0,
                                                     Z0, ZLD, 0L, NZ, Dd, 0);

    for (int t = 0; t < REPT; t++) {
        // AG = h_cat @ WhcSlim^T + bh_c  (fused over layers, N=2304 exact)
        gemm_bf16_nt<<<dim3(18, 32, 1), blk, SMEM_GEMM>>>(hsp, SH2, 0L, SH,
                                                          Whc, 0L, bhcAll, 0,
                                                          AG, NAG, 0L, NAG, SH, 0);
        // U[l] = h_prev[l] @ [Wh_f;Wh_i;Wh_o][l]^T + bias  (batched over l)
        gemm_bf16_nt<<<dim3(6, 32, 3), blk, SMEM_GEMM>>>(hsp, SH2, (long)Hh, SH,
                                                         Whfio, (long)NU * (2 * Hh), bhfio, NU,
                                                         U, NU, (long)Bsz * NU, NU, Hh, 0);
        // G2 = Wh_g . h_cat + bh_g (9 tiny dots per row, fp32)
        glog2_kernel<<<(Bsz * 9 * 32 + 255) / 256, blk>>>(hf, Wh_g, bh_g, G2);

        for (int l = 0; l < Ss; l++) {
            const float* Zl = Z0;
            if (l > 0) {
                gemm_bf16_nt<<<dim3(9, 32, 1), blk, SMEM_GEMM>>>(
                    hsp + (size_t)(l - 1) * Hh, SH2, 0L, SH,
                    WiAll + (size_t)l * NZ * (2 * Dd), 0L,
                    biAll + l * NZ, 0,
                    Z, ZLD, 0L, NZ, Dd, 0);
                Zl = Z;
            }
            __nv_bfloat16* fptr = (l == Ss - 1 && t < REPT - 1) ? featsp : nullptr;
            cell_kernel<<<(Bsz * Hh + 255) / 256, blk>>>(
                Zl, U + (size_t)l * Bsz * NU, AG, G2,
                hsp, hf, c, fptr, l, t);
        }
    }

    // out = sigmoid(feat @ W_last^T + b_last)
    gemm_bf16_nt<<<dim3(1, 32, 1), blk, SMEM_GEMM>>>(featsp, FEATW2, 0L, FEATK,
                                                     Wlast, 0L, b_last, 0,
                                                     out, OUTN, 0L, OUTN, FEATK, 1);
}

// round 5
// speedup vs baseline: 2.8194x; 1.0041x over previous
#include <cuda_runtime.h>
#include <cuda_bf16.h>
#include <math.h>
#include <stdint.h>

// Problem constants
#define Bsz  4096
#define Dd   256
#define Hh   256
#define Ss   3
#define REPT 10
#define OUTN 44
#define SH   768      // S*H
#define NZS  1024     // slim Z rows: f,i,o,c
#define NU   768
#define NAG  2304     // fused AG: 3 layers x 768 aux rows
#define FEATK 2304    // (REP-1)*H
#define SH2  1536     // split h row: [hi(768) | lo(768)]
#define XW2  512      // split x row: [hi(256) | lo(256)]

// ---------------- scratch (static device arrays; no cudaMalloc) ------------
__device__ __nv_bfloat16 g_hsp[(size_t)Bsz * SH2];
__device__ float         g_hf[(size_t)Bsz * SH];     // fp32 h_cat copy
__device__ __nv_bfloat16 g_xsp[(size_t)Bsz * XW2];
__device__ float         g_c[(size_t)Bsz * SH];
__device__ float         g_U[(size_t)Ss * Bsz * NU];
__device__ float         g_AG[(size_t)Bsz * NAG];
__device__ float         g_G2[(size_t)Bsz * 12];     // Wh_g . h_cat + bh_g (9 used)
__device__ float         g_G0[(size_t)Bsz * 3];      // Wi_g[0] . x + bi_g[0]
__device__ float         g_Z[(size_t)Bsz * NZS];
__device__ float         g_Z0[(size_t)Bsz * NZS];
__device__ float         g_featf[(size_t)Bsz * FEATK];
__device__ __nv_bfloat16 g_WiAll[(size_t)Ss * NZS * (2*Dd)];
__device__ float         g_biAll[Ss * NZS];
__device__ __nv_bfloat16 g_Whfio[(size_t)Ss * NU * (2*Hh)];
__device__ float         g_bhfio[Ss * NU];
__device__ __nv_bfloat16 g_Whc[(size_t)NAG * (2*SH)];

__device__ __forceinline__ float sigf(float x) { return 1.0f / (1.0f + expf(-x)); }

__device__ __forceinline__ void split_bf16(float v, __nv_bfloat16& hi, __nv_bfloat16& lo) {
    hi = __float2bfloat16(v);
    lo = __float2bfloat16(v - __bfloat162float(hi));
}

// ---------------- bf16 HMMA GEMM:  C = A' @ W'^T + bias --------------------
// Split-K3: logical A row = [Ah(K) | Al(K) | Ah(K)], W row = [Wh|Wh|Wl].
// A: hi at +0, lo at +loOff (row stride lda). W: [N][2K], hi|lo.
// CTA tile 128x256x64, 8 warps (warp 64x64), 3-stage cp.async, no N raggedness
// (gridDim.x * 256 == N exactly; M == 4096 exactly).
#define BM 128
#define BN 256
#define BKE 64
#define SAS 72                      // smem row stride (elems): 64 + 8 pad
#define SA_SZ (BM * SAS)            // 9216 elems
#define SB_SZ (BN * SAS)            // 18432 elems
#define STG_E (SA_SZ + SB_SZ)       // 27648 elems
#define SMEM_GEMM (3 * STG_E * 2)   // 165888 bytes

#define LDSM4(r0,r1,r2,r3,addr) \
  asm volatile("ldmatrix.sync.aligned.m8n8.x4.shared.b16 {%0,%1,%2,%3}, [%4];" \
   : "=r"(r0),"=r"(r1),"=r"(r2),"=r"(r3) : "r"(addr))

#define MMA16816(d, a, b) \
  asm volatile("mma.sync.aligned.m16n8k16.row.col.f32.bf16.bf16.f32 " \
    "{%0,%1,%2,%3}, {%4,%5,%6,%7}, {%8,%9}, {%0,%1,%2,%3};" \
    : "+f"(d[0]),"+f"(d[1]),"+f"(d[2]),"+f"(d[3]) \
    : "r"(a[0]),"r"(a[1]),"r"(a[2]),"r"(a[3]), "r"(b[0]),"r"(b[1]))

__global__ void __launch_bounds__(256, 1)
gemm256(const __nv_bfloat16* __restrict__ A, int lda, long sA, int loOff,
        const __nv_bfloat16* __restrict__ W, long sW,
        const float* __restrict__ bias, int sBias,
        float* __restrict__ C, int ldc, long sC, int K)
{
    extern __shared__ __align__(16) __nv_bfloat16 smem[];

    const int z = blockIdx.z;
    A += (size_t)z * sA;
    W += (size_t)z * sW;
    C += (size_t)z * sC;
    const float* bz = bias + (size_t)z * sBias;

    const int m0 = blockIdx.y * BM;
    const int n0 = blockIdx.x * BN;
    const int tid  = threadIdx.x;
    const int warp = tid >> 5;
    const int lane = tid & 31;
    const int wm = warp & 1;    // 2 warp-rows of 64
    const int wn = warp >> 1;   // 4 warp-cols of 64

    const int ktPerSeg = K / BKE;
    const int KT = 3 * ktPerSeg;
    const int W2 = 2 * K;

    float acc[4][8][4];
#pragma unroll
    for (int mi = 0; mi < 4; mi++)
#pragma unroll
        for (int ni = 0; ni < 8; ni++)
#pragma unroll
            for (int q = 0; q < 4; q++) acc[mi][ni][q] = 0.f;

    auto load_tiles = [&](int kt, int s) {
        int seg = kt / ktPerSeg;
        int kk  = (kt - seg * ktPerSeg) * BKE;
        const __nv_bfloat16* Ap = A + (seg == 1 ? loOff : 0) + kk;
        const __nv_bfloat16* Wp = W + (seg == 2 ? K : 0) + kk;
        __nv_bfloat16* sa0 = smem + s * STG_E;
        __nv_bfloat16* sb0 = sa0 + SA_SZ;
#pragma unroll
        for (int i = 0; i < 4; i++) {           // A: 128 rows x 8 chunks
            int idx = tid + i * 256;
            int row = idx >> 3;
            int ch  = idx & 7;
            unsigned sa = (unsigned)__cvta_generic_to_shared(&sa0[row * SAS + ch * 8]);
            const void* ga = Ap + (size_t)(m0 + row) * lda + ch * 8;
            asm volatile("cp.async.cg.shared.global [%0], [%1], 16;" :: "r"(sa), "l"(ga));
        }
#pragma unroll
        for (int i = 0; i < 8; i++) {           // B: 256 rows x 8 chunks
            int idx = tid + i * 256;
            int row = idx >> 3;
            int ch  = idx & 7;
            unsigned sb = (unsigned)__cvta_generic_to_shared(&sb0[row * SAS + ch * 8]);
            const void* gw = Wp + (size_t)(n0 + row) * W2 + ch * 8;
            asm volatile("cp.async.cg.shared.global [%0], [%1], 16;" :: "r"(sb), "l"(gw));
        }
        asm volatile("cp.async.commit_group;");
    };

    load_tiles(0, 0);
    load_tiles(1, 1);

    const int lt  = lane >> 3;
    const int lr  = lane & 7;

    int s = 0;
    for (int kt = 0; kt < KT; kt++) {
        asm volatile("cp.async.wait_group 1;");
        __syncthreads();

        const __nv_bfloat16* pa = smem + s * STG_E;
        const __nv_bfloat16* pb = pa + SA_SZ;
#pragma unroll
        for (int kq = 0; kq < 4; kq++) {
            const int k0 = kq * 16;
            unsigned af[4][4];
#pragma unroll
            for (int mi = 0; mi < 4; mi++) {
                int mrow = wm * 64 + mi * 16 + (lt & 1) * 8 + lr;
                int kcol = k0 + (lt >> 1) * 8;
                unsigned addr = (unsigned)__cvta_generic_to_shared(&pa[mrow * SAS + kcol]);
                LDSM4(af[mi][0], af[mi][1], af[mi][2], af[mi][3], addr);
            }
            unsigned bf[8][2];
#pragma unroll
            for (int nb = 0; nb < 4; nb++) {
                int nrow = wn * 64 + nb * 16 + (lt >> 1) * 8 + lr;
                int kcol = k0 + (lt & 1) * 8;
                unsigned addr = (unsigned)__cvta_generic_to_shared(&pb[nrow * SAS + kcol]);
                unsigned r0, r1, r2, r3;
                LDSM4(r0, r1, r2, r3, addr);
                bf[nb * 2][0] = r0;     bf[nb * 2][1] = r1;
                bf[nb * 2 + 1][0] = r2; bf[nb * 2 + 1][1] = r3;
            }
#pragma unroll
            for (int mi = 0; mi < 4; mi++)
#pragma unroll
                for (int ni = 0; ni < 8; ni++)
                    MMA16816(acc[mi][ni], af[mi], bf[ni]);
        }
        // stage (kt+2)%3 last held tile kt-1; all warps are past this iter's
        // barrier only after consuming tile kt-1 -> safe to overwrite.
        if (kt + 2 < KT) load_tiles(kt + 2, (s + 2 >= 3) ? s - 1 : s + 2);
        else asm volatile("cp.async.commit_group;");
        if (++s == 3) s = 0;
    }

    // ---- epilogue ----
#pragma unroll
    for (int mi = 0; mi < 4; mi++) {
        const int r0 = m0 + wm * 64 + mi * 16 + (lane >> 2);
#pragma unroll
        for (int ni = 0; ni < 8; ni++) {
            const int cc = n0 + wn * 64 + ni * 8 + (lane & 3) * 2;
            const float* a = acc[mi][ni];
            float b0 = bz[cc], b1 = bz[cc + 1];
            C[(size_t)r0 * ldc + cc]           = a[0] + b0;
            C[(size_t)r0 * ldc + cc + 1]       = a[1] + b1;
            C[(size_t)(r0 + 8) * ldc + cc]     = a[2] + b0;
            C[(size_t)(r0 + 8) * ldc + cc + 1] = a[3] + b1;
        }
    }
}

// ---------------- small fp32 dot kernels ------------------------------------
// G2[b][o] = Wh_g[o] . h_cat[b] + bh_g[o], o < 9
__global__ void glog2_kernel(const float* __restrict__ hf,
                             const float* __restrict__ whg,
                             const float* __restrict__ bhg,
                             float* __restrict__ G2)
{
    int gw = (blockIdx.x * blockDim.x + threadIdx.x) >> 5;
    int lane = threadIdx.x & 31;
    if (gw >= Bsz * 9) return;
    int b = gw / 9;
    int o = gw - b * 9;
    const float* hr = hf + (size_t)b * SH;
    const float* wr = whg + (size_t)o * SH;
    float sum = 0.f;
#pragma unroll 6
    for (int k = lane; k < SH; k += 32) sum += hr[k] * wr[k];
#pragma unroll
    for (int off = 16; off; off >>= 1) sum += __shfl_xor_sync(0xFFFFFFFFu, sum, off);
    if (lane == 0) G2[(size_t)b * 12 + o] = sum + bhg[o];
}

// G0[b][r] = Wi_g[0][r] . x[b] + bi_g[0][r], r < 3
__global__ void glog0_kernel(const float* __restrict__ x,
                             const float* __restrict__ wig,
                             const float* __restrict__ big,
                             float* __restrict__ G0)
{
    int gw = (blockIdx.x * blockDim.x + threadIdx.x) >> 5;
    int lane = threadIdx.x & 31;
    if (gw >= Bsz * 3) return;
    int b = gw / 3;
    int r = gw - b * 3;
    const float* xr = x + (size_t)b * Dd;
    const float* wr = wig + (size_t)r * Dd;
    float sum = 0.f;
#pragma unroll 4
    for (int k = lane; k < Dd; k += 32) sum += xr[k] * wr[k];
#pragma unroll
    for (int off = 16; off; off >>= 1) sum += __shfl_xor_sync(0xFFFFFFFFu, sum, off);
    if (lane == 0) G0[(size_t)b * 3 + r] = sum + big[r];
}

// out[b][o] = sigmoid(featf[b] . W_last[o] + b_last[o])
__global__ void out_kernel(const float* __restrict__ featf,
                           const float* __restrict__ wl,
                           const float* __restrict__ bl,
                           float* __restrict__ out)
{
    int gw = (blockIdx.x * blockDim.x + threadIdx.x) >> 5;
    int lane = threadIdx.x & 31;
    if (gw >= Bsz * OUTN) return;
    int b = gw / OUTN;
    int o = gw - b * OUTN;
    const float* fr = featf + (size_t)b * FEATK;
    const float* wr = wl + (size_t)o * FEATK;
    float sum = 0.f;
#pragma unroll 8
    for (int k = lane; k < FEATK; k += 32) sum += fr[k] * wr[k];
#pragma unroll
    for (int off = 16; off; off >>= 1) sum += __shfl_xor_sync(0xFFFFFFFFu, sum, off);
    if (lane == 0) out[(size_t)b * OUTN + o] = sigf(sum + bl[o]);
}

// ---------------- state init / splits --------------------------------------
__global__ void init_state(const float* __restrict__ hid, const float* __restrict__ cur,
                           __nv_bfloat16* __restrict__ hsp, float* __restrict__ hf,
                           float* __restrict__ c)
{
    int i = blockIdx.x * blockDim.x + threadIdx.x;
    const int total = Ss * Bsz * Hh;
    if (i >= total) return;
    int l = i / (Bsz * Hh);
    int r = i - l * (Bsz * Hh);
    int b = r >> 8;
    int j = r & 255;
    __nv_bfloat16 hi, lo;
    float v = hid[i];
    split_bf16(v, hi, lo);
    hsp[(size_t)b * SH2 + l * Hh + j] = hi;
    hsp[(size_t)b * SH2 + SH + l * Hh + j] = lo;
    hf[(size_t)b * SH + l * Hh + j] = v;
    c[(size_t)b * SH + l * Hh + j] = cur[i];
}

__global__ void split_x(const float* __restrict__ x, __nv_bfloat16* __restrict__ xsp)
{
    int i = blockIdx.x * blockDim.x + threadIdx.x;
    if (i >= Bsz * Dd) return;
    int b = i >> 8, j = i & 255;
    __nv_bfloat16 hi, lo;
    split_bf16(x[i], hi, lo);
    xsp[(size_t)b * XW2 + j] = hi;
    xsp[(size_t)b * XW2 + Dd + j] = lo;
}

// ---------------- weight repacks (fp32 -> split bf16, concat rows) ---------
__global__ void repack_wi(const float* __restrict__ wf, const float* __restrict__ wi,
                          const float* __restrict__ wo, const float* __restrict__ wc,
                          __nv_bfloat16* __restrict__ out)
{
    int idx = blockIdx.x * blockDim.x + threadIdx.x;
    if (idx >= Ss * NZS * Dd) return;
    int k = idx % Dd;
    int r = (idx / Dd) % NZS;
    int l = idx / (Dd * NZS);
    float v;
    if      (r < 256) v = wf[((size_t)l * Hh + r)       * Dd + k];
    else if (r < 512) v = wi[((size_t)l * Hh + r - 256) * Dd + k];
    else if (r < 768) v = wo[((size_t)l * Hh + r - 512) * Dd + k];
    else              v = wc[((size_t)l * Hh + r - 768) * Dd + k];
    __nv_bfloat16 hi, lo;
    split_bf16(v, hi, lo);
    size_t o = ((size_t)l * NZS + r) * (2 * Dd) + k;
    out[o] = hi;
    out[o + Dd] = lo;
}

__global__ void repack_whfio(const float* __restrict__ wf, const float* __restrict__ wi,
                             const float* __restrict__ wo, __nv_bfloat16* __restrict__ out)
{
    int idx = blockIdx.x * blockDim.x + threadIdx.x;
    if (idx >= Ss * NU * Hh) return;
    int k = idx % Hh;
    int r = (idx / Hh) % NU;
    int l = idx / (Hh * NU);
    float v;
    if      (r < 256) v = wf[((size_t)l * Hh + r)       * Hh + k];
    else if (r < 512) v = wi[((size_t)l * Hh + r - 256) * Hh + k];
    else              v = wo[((size_t)l * Hh + r - 512) * Hh + k];
    __nv_bfloat16 hi, lo;
    split_bf16(v, hi, lo);
    size_t o = ((size_t)l * NU + r) * (2 * Hh) + k;
    out[o] = hi;
    out[o + Hh] = lo;
}

__global__ void repack_whc(const float* __restrict__ wc, __nv_bfloat16* __restrict__ out)
{
    int idx = blockIdx.x * blockDim.x + threadIdx.x;
    if (idx >= NAG * SH) return;
    int k = idx % SH;
    int r = idx / SH;
    float v = wc[(size_t)r * SH + k];   // Wh_c: [3][768][768] == [2304][768]
    __nv_bfloat16 hi, lo;
    split_bf16(v, hi, lo);
    size_t o = (size_t)r * (2 * SH) + k;
    out[o] = hi;
    out[o + SH] = lo;
}

__global__ void repack_bias(const float* __restrict__ bif, const float* __restrict__ bii,
                            const float* __restrict__ bio, const float* __restrict__ bic,
                            const float* __restrict__ bhf, const float* __restrict__ bhi,
                            const float* __restrict__ bho,
                            float* __restrict__ biAll, float* __restrict__ bhfio)
{
    int idx = blockIdx.x * blockDim.x + threadIdx.x;
    const int n1 = Ss * NZS;
    const int n2 = n1 + Ss * NU;
    if (idx < n1) {
        int r = idx % NZS, l = idx / NZS;
        float v;
        if      (r < 256) v = bif[l * Hh + r];
        else if (r < 512) v = bii[l * Hh + r - 256];
        else if (r < 768) v = bio[l * Hh + r - 512];
        else              v = bic[l * Hh + r - 768];
        biAll[idx] = v;
    } else if (idx < n2) {
        int t = idx - n1;
        int r = t % NU, l = t / NU;
        float v;
        if      (r < 256) v = bhf[l * Hh + r];
        else if (r < 512) v = bhi[l * Hh + r - 256];
        else              v = bho[l * Hh + r - 512];
        bhfio[t] = v;
    }
}

// ---------------- per-layer LSTM cell (block = one batch row) --------------
__global__ void __launch_bounds__(256)
cell_kernel(const float* __restrict__ Z, const float* __restrict__ U,
            const float* __restrict__ AG, const float* __restrict__ G2,
            const float* __restrict__ G0,
            const float* __restrict__ wig3, const float* __restrict__ big3,
            const float* __restrict__ hin,
            __nv_bfloat16* __restrict__ hsp, float* __restrict__ hf,
            float* __restrict__ c, float* __restrict__ featf, int l, int t)
{
    const int b = blockIdx.x;
    const int j = threadIdx.x;
    const int warp = j >> 5;
    const int lane = j & 31;
    __shared__ float red[3][8];

    float gin0, gin1, gin2;
    if (l == 0) {
        gin0 = G0[(size_t)b * 3 + 0];
        gin1 = G0[(size_t)b * 3 + 1];
        gin2 = G0[(size_t)b * 3 + 2];
    } else {
        float iv = hin[(size_t)b * SH + j];
        float p0 = iv * wig3[j];
        float p1 = iv * wig3[256 + j];
        float p2 = iv * wig3[512 + j];
#pragma unroll
        for (int off = 16; off; off >>= 1) {
            p0 += __shfl_xor_sync(0xFFFFFFFFu, p0, off);
            p1 += __shfl_xor_sync(0xFFFFFFFFu, p1, off);
            p2 += __shfl_xor_sync(0xFFFFFFFFu, p2, off);
        }
        if (lane == 0) { red[0][warp] = p0; red[1][warp] = p1; red[2][warp] = p2; }
        __syncthreads();
        float s0 = 0.f, s1 = 0.f, s2 = 0.f;
#pragma unroll
        for (int w = 0; w < 8; w++) { s0 += red[0][w]; s1 += red[1][w]; s2 += red[2][w]; }
        gin0 = s0 + big3[0];
        gin1 = s1 + big3[1];
        gin2 = s2 + big3[2];
    }

    const float* Zb = Z + (size_t)b * NZS;
    const float* Ub = U + (size_t)b * NU;
    const float* Gb = AG + (size_t)b * NAG + l * SH;
    const float* g2 = G2 + (size_t)b * 12 + l * 3;

    float g0 = sigf(gin0 + g2[0]);
    float g1 = sigf(gin1 + g2[1]);
    float g2v = sigf(gin2 + g2[2]);
    float aux = g0 * Gb[j] + g1 * Gb[256 + j] + g2v * Gb[512 + j];

    float fg = sigf(Zb[j]       + Ub[j]);
    float ig = sigf(Zb[256 + j] + Ub[256 + j]);
    float og = sigf(Zb[512 + j] + Ub[512 + j]);
    float ct = tanhf(Zb[768 + j] + aux);

    size_t sidx = (size_t)b * SH + l * Hh + j;
    float cn = fg * c[sidx] + ig * ct;
    float hn = og * cn;
    c[sidx] = cn;
    hf[sidx] = hn;

    __nv_bfloat16 hh, hl;
    split_bf16(hn, hh, hl);
    hsp[(size_t)b * SH2 + l * Hh + j] = hh;
    hsp[(size_t)b * SH2 + SH + l * Hh + j] = hl;
    if (featf) featf[(size_t)b * FEATK + t * Hh + j] = hn;
}

// ---------------- orchestration --------------------------------------------
extern "C" void kernel_launch(void* const* d_in, const int* in_sizes, int n_in,
                              void* d_out, int out_size)
{
    (void)in_sizes; (void)n_in; (void)out_size;
    const float* x    = (const float*)d_in[0];
    const float* hid0 = (const float*)d_in[1];
    const float* cur0 = (const float*)d_in[2];
    const float* Wi_f = (const float*)d_in[3];
    const float* bi_f = (const float*)d_in[4];
    const float* Wi_i = (const float*)d_in[5];
    const float* bi_i = (const float*)d_in[6];
    const float* Wi_o = (const float*)d_in[7];
    const float* bi_o = (const float*)d_in[8];
    const float* Wi_c = (const float*)d_in[9];
    const float* bi_c = (const float*)d_in[10];
    const float* Wi_g = (const float*)d_in[11];
    const float* bi_g = (const float*)d_in[12];
    const float* Wh_f = (const float*)d_in[13];
    const float* bh_f = (const float*)d_in[14];
    const float* Wh_i = (const float*)d_in[15];
    const float* bh_i = (const float*)d_in[16];
    const float* Wh_o = (const float*)d_in[17];
    const float* bh_o = (const float*)d_in[18];
    const float* Wh_g = (const float*)d_in[19];
    const float* bh_g = (const float*)d_in[20];
    const float* Wh_c = (const float*)d_in[21];
    const float* bh_c = (const float*)d_in[22];
    const float* W_last = (const float*)d_in[23];
    const float* b_last = (const float*)d_in[24];
    float* out = (float*)d_out;

    __nv_bfloat16 *hsp, *xsp, *WiAll, *Whfio, *Whc;
    float *hf, *c, *U, *AG, *G2, *G0, *Z, *Z0, *featf, *biAll, *bhfio;
    cudaGetSymbolAddress((void**)&hsp,   g_hsp);
    cudaGetSymbolAddress((void**)&hf,    g_hf);
    cudaGetSymbolAddress((void**)&xsp,   g_xsp);
    cudaGetSymbolAddress((void**)&c,     g_c);
    cudaGetSymbolAddress((void**)&U,     g_U);
    cudaGetSymbolAddress((void**)&AG,    g_AG);
    cudaGetSymbolAddress((void**)&G2,    g_G2);
    cudaGetSymbolAddress((void**)&G0,    g_G0);
    cudaGetSymbolAddress((void**)&Z,     g_Z);
    cudaGetSymbolAddress((void**)&Z0,    g_Z0);
    cudaGetSymbolAddress((void**)&featf, g_featf);
    cudaGetSymbolAddress((void**)&WiAll, g_WiAll);
    cudaGetSymbolAddress((void**)&biAll, g_biAll);
    cudaGetSymbolAddress((void**)&Whfio, g_Whfio);
    cudaGetSymbolAddress((void**)&bhfio, g_bhfio);
    cudaGetSymbolAddress((void**)&Whc,   g_Whc);

    cudaFuncSetAttribute(gemm256, cudaFuncAttributeMaxDynamicSharedMemorySize, SMEM_GEMM);

    const dim3 blk(256);

    init_state<<<(Ss * Bsz * Hh + 255) / 256, blk>>>(hid0, cur0, hsp, hf, c);
    split_x<<<(Bsz * Dd + 255) / 256, blk>>>(x, xsp);
    repack_wi<<<(Ss * NZS * Dd + 255) / 256, blk>>>(Wi_f, Wi_i, Wi_o, Wi_c, WiAll);
    repack_whfio<<<(Ss * NU * Hh + 255) / 256, blk>>>(Wh_f, Wh_i, Wh_o, Whfio);
    repack_whc<<<(NAG * SH + 255) / 256, blk>>>(Wh_c, Whc);
    repack_bias<<<(Ss * (NZS + NU) + 255) / 256, blk>>>(
        bi_f, bi_i, bi_o, bi_c, bh_f, bh_i, bh_o, biAll, bhfio);

    // time-invariant layer-0 input preacts
    gemm256<<<dim3(4, 32, 1), blk, SMEM_GEMM>>>(xsp, XW2, 0L, Dd,
                                                WiAll, 0L, biAll, 0,
                                                Z0, NZS, 0L, Dd);
    glog0_kernel<<<(Bsz * 3 * 32 + 255) / 256, blk>>>(x, Wi_g, bi_g, G0);

    for (int t = 0; t < REPT; t++) {
        // AG = h_cat @ WhcSlim^T + bh_c  (fused over layers, N=2304 exact)
        gemm256<<<dim3(9, 32, 1), blk, SMEM_GEMM>>>(hsp, SH2, 0L, SH,
                                                    Whc, 0L, bh_c, 0,
                                                    AG, NAG, 0L, SH);
        // U[l] = h_prev[l] @ [Wh_f;Wh_i;Wh_o][l]^T + bias  (batched over l)
        gemm256<<<dim3(3, 32, 3), blk, SMEM_GEMM>>>(hsp, SH2, (long)Hh, SH,
                                                    Whfio, (long)NU * (2 * Hh), bhfio, NU,
                                                    U, NU, (long)Bsz * NU, Hh);
        // G2 = Wh_g . h_cat + bh_g
        glog2_kernel<<<(Bsz * 9 * 32 + 255) / 256, blk>>>(hf, Wh_g, bh_g, G2);

        for (int l = 0; l < Ss; l++) {
            const float* Zl = Z0;
            if (l > 0) {
                gemm256<<<dim3(4, 32, 1), blk, SMEM_GEMM>>>(
                    hsp + (size_t)(l - 1) * Hh, SH2, 0L, SH,
                    WiAll + (size_t)l * NZS * (2 * Dd), 0L,
                    biAll + l * NZS, 0,
                    Z, NZS, 0L, Dd);
                Zl = Z;
            }
            float* fptr = (l == Ss - 1 && t < REPT - 1) ? featf : nullptr;
            cell_kernel<<<Bsz, blk>>>(
                Zl, U + (size_t)l * Bsz * NU, AG, G2, G0,
                Wi_g + (size_t)l * 3 * Dd, bi_g + l * 3,
                (l > 0) ? (hf + (size_t)(l - 1) * Hh) : nullptr,
                hsp, hf, c, fptr, l, t);
        }
    }

    out_kernel<<<(Bsz * OUTN * 32 + 255) / 256, blk>>>(featf, W_last, b_last, out);
}

// round 6
// speedup vs baseline: 4.7561x; 1.6869x over previous
#include <cuda_runtime.h>
#include <cuda_fp16.h>
#include <math.h>
#include <stdint.h>

// Problem constants
#define Bsz  4096
#define Dd   256
#define Hh   256
#define Ss   3
#define REPT 10
#define OUTN 44
#define SH   768      // S*H
#define NZS  1024     // slim Z rows: f,i,o,c
#define NU   768
#define NAG  2304     // fused AG: 3 layers x 768 aux rows
#define FEATK 2304    // (REP-1)*H

// ---------------- scratch (static device arrays; no cudaMalloc) ------------
__device__ __half g_hsp[(size_t)Bsz * SH];        // fp16 hidden state (h_cat layout)
__device__ float  g_hf[(size_t)Bsz * SH];         // fp32 h_cat copy
__device__ __half g_xsp[(size_t)Bsz * Dd];        // fp16 x
__device__ float  g_c[(size_t)Bsz * SH];
__device__ float  g_U[(size_t)Ss * Bsz * NU];
__device__ float  g_AG[(size_t)Bsz * NAG];
__device__ float  g_G2[(size_t)Bsz * 12];         // Wh_g . h_cat + bh_g (9 used)
__device__ float  g_G0[(size_t)Bsz * 3];          // Wi_g[0] . x + bi_g[0]
__device__ float  g_Z[(size_t)Bsz * NZS];
__device__ float  g_Z0[(size_t)Bsz * NZS];
__device__ float  g_featf[(size_t)Bsz * FEATK];
__device__ __half g_WiAll[(size_t)Ss * NZS * Dd];
__device__ float  g_biAll[Ss * NZS];
__device__ __half g_Whfio[(size_t)Ss * NU * Hh];
__device__ float  g_bhfio[Ss * NU];
__device__ __half g_Whc[(size_t)NAG * SH];

__device__ __forceinline__ float sigf(float x) { return 1.0f / (1.0f + expf(-x)); }

// ---------------- fp16 HMMA GEMM:  C = A @ W^T + bias ----------------------
// A: [M x K] fp16 row-major (row stride lda). W: [N x K] fp16 row-major.
// CTA tile 128x256x64, 8 warps (warp 64x64), 3-stage cp.async.
// gridDim.x * 256 == N exactly; M == 4096 exactly; K % 64 == 0.
#define BM 128
#define BN 256
#define BKE 64
#define SAS 72                      // smem row stride (elems): 64 + 8 pad
#define SA_SZ (BM * SAS)
#define SB_SZ (BN * SAS)
#define STG_E (SA_SZ + SB_SZ)       // 27648 elems
#define SMEM_GEMM (3 * STG_E * 2)   // 165888 bytes

#define LDSM4(r0,r1,r2,r3,addr) \
  asm volatile("ldmatrix.sync.aligned.m8n8.x4.shared.b16 {%0,%1,%2,%3}, [%4];" \
   : "=r"(r0),"=r"(r1),"=r"(r2),"=r"(r3) : "r"(addr))

#define MMA16816(d, a, b) \
  asm volatile("mma.sync.aligned.m16n8k16.row.col.f32.f16.f16.f32 " \
    "{%0,%1,%2,%3}, {%4,%5,%6,%7}, {%8,%9}, {%0,%1,%2,%3};" \
    : "+f"(d[0]),"+f"(d[1]),"+f"(d[2]),"+f"(d[3]) \
    : "r"(a[0]),"r"(a[1]),"r"(a[2]),"r"(a[3]), "r"(b[0]),"r"(b[1]))

__global__ void __launch_bounds__(256, 1)
gemm256(const __half* __restrict__ A, int lda, long sA,
        const __half* __restrict__ W, long sW,
        const float* __restrict__ bias, int sBias,
        float* __restrict__ C, int ldc, long sC, int K)
{
    extern __shared__ __align__(16) __half smem[];

    const int z = blockIdx.z;
    A += (size_t)z * sA;
    W += (size_t)z * sW;
    C += (size_t)z * sC;
    const float* bz = bias + (size_t)z * sBias;

    const int m0 = blockIdx.y * BM;
    const int n0 = blockIdx.x * BN;
    const int tid  = threadIdx.x;
    const int warp = tid >> 5;
    const int lane = tid & 31;
    const int wm = warp & 1;    // 2 warp-rows of 64
    const int wn = warp >> 1;   // 4 warp-cols of 64

    const int KT = K / BKE;

    float acc[4][8][4];
#pragma unroll
    for (int mi = 0; mi < 4; mi++)
#pragma unroll
        for (int ni = 0; ni < 8; ni++)
#pragma unroll
            for (int q = 0; q < 4; q++) acc[mi][ni][q] = 0.f;

    auto load_tiles = [&](int kt, int s) {
        const __half* Ap = A + kt * BKE;
        const __half* Wp = W + kt * BKE;
        __half* sa0 = smem + s * STG_E;
        __half* sb0 = sa0 + SA_SZ;
#pragma unroll
        for (int i = 0; i < 4; i++) {           // A: 128 rows x 8 chunks of 16B
            int idx = tid + i * 256;
            int row = idx >> 3;
            int ch  = idx & 7;
            unsigned sa = (unsigned)__cvta_generic_to_shared(&sa0[row * SAS + ch * 8]);
            const void* ga = Ap + (size_t)(m0 + row) * lda + ch * 8;
            asm volatile("cp.async.cg.shared.global [%0], [%1], 16;" :: "r"(sa), "l"(ga));
        }
#pragma unroll
        for (int i = 0; i < 8; i++) {           // B: 256 rows x 8 chunks
            int idx = tid + i * 256;
            int row = idx >> 3;
            int ch  = idx & 7;
            unsigned sb = (unsigned)__cvta_generic_to_shared(&sb0[row * SAS + ch * 8]);
            const void* gw = Wp + (size_t)(n0 + row) * K + ch * 8;
            asm volatile("cp.async.cg.shared.global [%0], [%1], 16;" :: "r"(sb), "l"(gw));
        }
        asm volatile("cp.async.commit_group;");
    };

    load_tiles(0, 0);
    load_tiles(1, 1);

    const int lt  = lane >> 3;
    const int lr  = lane & 7;

    int s = 0;
    for (int kt = 0; kt < KT; kt++) {
        asm volatile("cp.async.wait_group 1;");
        __syncthreads();

        const __half* pa = smem + s * STG_E;
        const __half* pb = pa + SA_SZ;
#pragma unroll
        for (int kq = 0; kq < 4; kq++) {
            const int k0 = kq * 16;
            unsigned af[4][4];
#pragma unroll
            for (int mi = 0; mi < 4; mi++) {
                int mrow = wm * 64 + mi * 16 + (lt & 1) * 8 + lr;
                int kcol = k0 + (lt >> 1) * 8;
                unsigned addr = (unsigned)__cvta_generic_to_shared(&pa[mrow * SAS + kcol]);
                LDSM4(af[mi][0], af[mi][1], af[mi][2], af[mi][3], addr);
            }
            unsigned bf[8][2];
#pragma unroll
            for (int nb = 0; nb < 4; nb++) {
                int nrow = wn * 64 + nb * 16 + (lt >> 1) * 8 + lr;
                int kcol = k0 + (lt & 1) * 8;
                unsigned addr = (unsigned)__cvta_generic_to_shared(&pb[nrow * SAS + kcol]);
                unsigned r0, r1, r2, r3;
                LDSM4(r0, r1, r2, r3, addr);
                bf[nb * 2][0] = r0;     bf[nb * 2][1] = r1;
                bf[nb * 2 + 1][0] = r2; bf[nb * 2 + 1][1] = r3;
            }
#pragma unroll
            for (int mi = 0; mi < 4; mi++)
#pragma unroll
                for (int ni = 0; ni < 8; ni++)
                    MMA16816(acc[mi][ni], af[mi], bf[ni]);
        }
        // stage (kt+2)%3 last held tile kt-1; all warps are past this iter's
        // barrier only after consuming tile kt-1 -> safe to overwrite.
        if (kt + 2 < KT) load_tiles(kt + 2, (s + 2 >= 3) ? s - 1 : s + 2);
        else asm volatile("cp.async.commit_group;");
        if (++s == 3) s = 0;
    }

    // ---- epilogue ----
#pragma unroll
    for (int mi = 0; mi < 4; mi++) {
        const int r0 = m0 + wm * 64 + mi * 16 + (lane >> 2);
#pragma unroll
        for (int ni = 0; ni < 8; ni++) {
            const int cc = n0 + wn * 64 + ni * 8 + (lane & 3) * 2;
            const float* a = acc[mi][ni];
            float b0 = bz[cc], b1 = bz[cc + 1];
            C[(size_t)r0 * ldc + cc]           = a[0] + b0;
            C[(size_t)r0 * ldc + cc + 1]       = a[1] + b1;
            C[(size_t)(r0 + 8) * ldc + cc]     = a[2] + b0;
            C[(size_t)(r0 + 8) * ldc + cc + 1] = a[3] + b1;
        }
    }
}

// ---------------- small fp32 dot kernels ------------------------------------
__global__ void glog2_kernel(const float* __restrict__ hf,
                             const float* __restrict__ whg,
                             const float* __restrict__ bhg,
                             float* __restrict__ G2)
{
    int gw = (blockIdx.x * blockDim.x + threadIdx.x) >> 5;
    int lane = threadIdx.x & 31;
    if (gw >= Bsz * 9) return;
    int b = gw / 9;
    int o = gw - b * 9;
    const float* hr = hf + (size_t)b * SH;
    const float* wr = whg + (size_t)o * SH;
    float sum = 0.f;
#pragma unroll 6
    for (int k = lane; k < SH; k += 32) sum += hr[k] * wr[k];
#pragma unroll
    for (int off = 16; off; off >>= 1) sum += __shfl_xor_sync(0xFFFFFFFFu, sum, off);
    if (lane == 0) G2[(size_t)b * 12 + o] = sum + bhg[o];
}

__global__ void glog0_kernel(const float* __restrict__ x,
                             const float* __restrict__ wig,
                             const float* __restrict__ big,
                             float* __restrict__ G0)
{
    int gw = (blockIdx.x * blockDim.x + threadIdx.x) >> 5;
    int lane = threadIdx.x & 31;
    if (gw >= Bsz * 3) return;
    int b = gw / 3;
    int r = gw - b * 3;
    const float* xr = x + (size_t)b * Dd;
    const float* wr = wig + (size_t)r * Dd;
    float sum = 0.f;
#pragma unroll 4
    for (int k = lane; k < Dd; k += 32) sum += xr[k] * wr[k];
#pragma unroll
    for (int off = 16; off; off >>= 1) sum += __shfl_xor_sync(0xFFFFFFFFu, sum, off);
    if (lane == 0) G0[(size_t)b * 3 + r] = sum + big[r];
}

__global__ void out_kernel(const float* __restrict__ featf,
                           const float* __restrict__ wl,
                           const float* __restrict__ bl,
                           float* __restrict__ out)
{
    int gw = (blockIdx.x * blockDim.x + threadIdx.x) >> 5;
    int lane = threadIdx.x & 31;
    if (gw >= Bsz * OUTN) return;
    int b = gw / OUTN;
    int o = gw - b * OUTN;
    const float* fr = featf + (size_t)b * FEATK;
    const float* wr = wl + (size_t)o * FEATK;
    float sum = 0.f;
#pragma unroll 8
    for (int k = lane; k < FEATK; k += 32) sum += fr[k] * wr[k];
#pragma unroll
    for (int off = 16; off; off >>= 1) sum += __shfl_xor_sync(0xFFFFFFFFu, sum, off);
    if (lane == 0) out[(size_t)b * OUTN + o] = sigf(sum + bl[o]);
}

// ---------------- state init / splits --------------------------------------
__global__ void init_state(const float* __restrict__ hid, const float* __restrict__ cur,
                           __half* __restrict__ hsp, float* __restrict__ hf,
                           float* __restrict__ c)
{
    int i = blockIdx.x * blockDim.x + threadIdx.x;
    const int total = Ss * Bsz * Hh;
    if (i >= total) return;
    int l = i / (Bsz * Hh);
    int r = i - l * (Bsz * Hh);
    int b = r >> 8;
    int j = r & 255;
    float v = hid[i];
    size_t dst = (size_t)b * SH + l * Hh + j;
    hsp[dst] = __float2half(v);
    hf[dst]  = v;
    c[dst]   = cur[i];
}

__global__ void conv_x(const float* __restrict__ x, __half* __restrict__ xsp)
{
    int i = blockIdx.x * blockDim.x + threadIdx.x;
    if (i >= Bsz * Dd) return;
    xsp[i] = __float2half(x[i]);
}

// ---------------- fused weight repack (fp32 -> fp16, concat rows) ----------
#define RW1 (Ss * NZS * Dd)            // WiAll
#define RW2 (RW1 + Ss * NU * Hh)       // Whfio
#define RW3 (RW2 + NAG * SH)           // Whc
#define RW4 (RW3 + Ss * NZS)           // biAll
#define RW5 (RW4 + Ss * NU)            // bhfio

__global__ void repack_all(const float* __restrict__ wif, const float* __restrict__ wii,
                           const float* __restrict__ wio, const float* __restrict__ wic,
                           const float* __restrict__ whf, const float* __restrict__ whi,
                           const float* __restrict__ who, const float* __restrict__ whc,
                           const float* __restrict__ bif, const float* __restrict__ bii,
                           const float* __restrict__ bio, const float* __restrict__ bic,
                           const float* __restrict__ bhf, const float* __restrict__ bhi,
                           const float* __restrict__ bho,
                           __half* __restrict__ WiAll, __half* __restrict__ Whfio,
                           __half* __restrict__ Whc,
                           float* __restrict__ biAll, float* __restrict__ bhfio)
{
    int idx = blockIdx.x * blockDim.x + threadIdx.x;
    if (idx < RW1) {
        int k = idx % Dd;
        int r = (idx / Dd) % NZS;
        int l = idx / (Dd * NZS);
        float v;
        if      (r < 256) v = wif[((size_t)l * Hh + r)       * Dd + k];
        else if (r < 512) v = wii[((size_t)l * Hh + r - 256) * Dd + k];
        else if (r < 768) v = wio[((size_t)l * Hh + r - 512) * Dd + k];
        else              v = wic[((size_t)l * Hh + r - 768) * Dd + k];
        WiAll[idx] = __float2half(v);
    } else if (idx < RW2) {
        int t = idx - RW1;
        int k = t % Hh;
        int r = (t / Hh) % NU;
        int l = t / (Hh * NU);
        float v;
        if      (r < 256) v = whf[((size_t)l * Hh + r)       * Hh + k];
        else if (r < 512) v = whi[((size_t)l * Hh + r - 256) * Hh + k];
        else              v = who[((size_t)l * Hh + r - 512) * Hh + k];
        Whfio[t] = __float2half(v);
    } else if (idx < RW3) {
        int t = idx - RW2;
        Whc[t] = __float2half(whc[t]);   // Wh_c: [3][768][768] == [2304][768]
    } else if (idx < RW4) {
        int t = idx - RW3;
        int r = t % NZS, l = t / NZS;
        float v;
        if      (r < 256) v = bif[l * Hh + r];
        else if (r < 512) v = bii[l * Hh + r - 256];
        else if (r < 768) v = bio[l * Hh + r - 512];
        else              v = bic[l * Hh + r - 768];
        biAll[t] = v;
    } else if (idx < RW5) {
        int t = idx - RW4;
        int r = t % NU, l = t / NU;
        float v;
        if      (r < 256) v = bhf[l * Hh + r];
        else if (r < 512) v = bhi[l * Hh + r - 256];
        else              v = bho[l * Hh + r - 512];
        bhfio[t] = v;
    }
}

// ---------------- per-layer LSTM cell (block = one batch row) --------------
__global__ void __launch_bounds__(256)
cell_kernel(const float* __restrict__ Z, const float* __restrict__ U,
            const float* __restrict__ AG, const float* __restrict__ G2,
            const float* __restrict__ G0,
            const float* __restrict__ wig3, const float* __restrict__ big3,
            const float* __restrict__ hin,
            __half* __restrict__ hsp, float* __restrict__ hf,
            float* __restrict__ c, float* __restrict__ featf, int l, int t)
{
    const int b = blockIdx.x;
    const int j = threadIdx.x;
    const int warp = j >> 5;
    const int lane = j & 31;
    __shared__ float red[3][8];

    float gin0, gin1, gin2;
    if (l == 0) {
        gin0 = G0[(size_t)b * 3 + 0];
        gin1 = G0[(size_t)b * 3 + 1];
        gin2 = G0[(size_t)b * 3 + 2];
    } else {
        float iv = hin[(size_t)b * SH + j];
        float p0 = iv * wig3[j];
        float p1 = iv * wig3[256 + j];
        float p2 = iv * wig3[512 + j];
#pragma unroll
        for (int off = 16; off; off >>= 1) {
            p0 += __shfl_xor_sync(0xFFFFFFFFu, p0, off);
            p1 += __shfl_xor_sync(0xFFFFFFFFu, p1, off);
            p2 += __shfl_xor_sync(0xFFFFFFFFu, p2, off);
        }
        if (lane == 0) { red[0][warp] = p0; red[1][warp] = p1; red[2][warp] = p2; }
        __syncthreads();
        float s0 = 0.f, s1 = 0.f, s2 = 0.f;
#pragma unroll
        for (int w = 0; w < 8; w++) { s0 += red[0][w]; s1 += red[1][w]; s2 += red[2][w]; }
        gin0 = s0 + big3[0];
        gin1 = s1 + big3[1];
        gin2 = s2 + big3[2];
    }

    const float* Zb = Z + (size_t)b * NZS;
    const float* Ub = U + (size_t)b * NU;
    const float* Gb = AG + (size_t)b * NAG + l * SH;
    const float* g2 = G2 + (size_t)b * 12 + l * 3;

    float g0 = sigf(gin0 + g2[0]);
    float g1 = sigf(gin1 + g2[1]);
    float g2v = sigf(gin2 + g2[2]);
    float aux = g0 * Gb[j] + g1 * Gb[256 + j] + g2v * Gb[512 + j];

    float fg = sigf(Zb[j]       + Ub[j]);
    float ig = sigf(Zb[256 + j] + Ub[256 + j]);
    float og = sigf(Zb[512 + j] + Ub[512 + j]);
    float ct = tanhf(Zb[768 + j] + aux);

    size_t sidx = (size_t)b * SH + l * Hh + j;
    float cn = fg * c[sidx] + ig * ct;
    float hn = og * cn;
    c[sidx] = cn;
    hf[sidx] = hn;
    hsp[sidx] = __float2half(hn);
    if (featf) featf[(size_t)b * FEATK + t * Hh + j] = hn;
}

// ---------------- orchestration --------------------------------------------
extern "C" void kernel_launch(void* const* d_in, const int* in_sizes, int n_in,
                              void* d_out, int out_size)
{
    (void)in_sizes; (void)n_in; (void)out_size;
    const float* x    = (const float*)d_in[0];
    const float* hid0 = (const float*)d_in[1];
    const float* cur0 = (const float*)d_in[2];
    const float* Wi_f = (const float*)d_in[3];
    const float* bi_f = (const float*)d_in[4];
    const float* Wi_i = (const float*)d_in[5];
    const float* bi_i = (const float*)d_in[6];
    const float* Wi_o = (const float*)d_in[7];
    const float* bi_o = (const float*)d_in[8];
    const float* Wi_c = (const float*)d_in[9];
    const float* bi_c = (const float*)d_in[10];
    const float* Wi_g = (const float*)d_in[11];
    const float* bi_g = (const float*)d_in[12];
    const float* Wh_f = (const float*)d_in[13];
    const float* bh_f = (const float*)d_in[14];
    const float* Wh_i = (const float*)d_in[15];
    const float* bh_i = (const float*)d_in[16];
    const float* Wh_o = (const float*)d_in[17];
    const float* bh_o = (const float*)d_in[18];
    const float* Wh_g = (const float*)d_in[19];
    const float* bh_g = (const float*)d_in[20];
    const float* Wh_c = (const float*)d_in[21];
    const float* bh_c = (const float*)d_in[22];
    const float* W_last = (const float*)d_in[23];
    const float* b_last = (const float*)d_in[24];
    float* out = (float*)d_out;

    __half *hsp, *xsp, *WiAll, *Whfio, *Whc;
    float *hf, *c, *U, *AG, *G2, *G0, *Z, *Z0, *featf, *biAll, *bhfio;
    cudaGetSymbolAddress((void**)&hsp,   g_hsp);
    cudaGetSymbolAddress((void**)&hf,    g_hf);
    cudaGetSymbolAddress((void**)&xsp,   g_xsp);
    cudaGetSymbolAddress((void**)&c,     g_c);
    cudaGetSymbolAddress((void**)&U,     g_U);
    cudaGetSymbolAddress((void**)&AG,    g_AG);
    cudaGetSymbolAddress((void**)&G2,    g_G2);
    cudaGetSymbolAddress((void**)&G0,    g_G0);
    cudaGetSymbolAddress((void**)&Z,     g_Z);
    cudaGetSymbolAddress((void**)&Z0,    g_Z0);
    cudaGetSymbolAddress((void**)&featf, g_featf);
    cudaGetSymbolAddress((void**)&WiAll, g_WiAll);
    cudaGetSymbolAddress((void**)&biAll, g_biAll);
    cudaGetSymbolAddress((void**)&Whfio, g_Whfio);
    cudaGetSymbolAddress((void**)&bhfio, g_bhfio);
    cudaGetSymbolAddress((void**)&Whc,   g_Whc);

    cudaFuncSetAttribute(gemm256, cudaFuncAttributeMaxDynamicSharedMemorySize, SMEM_GEMM);

    const dim3 blk(256);

    // setup (5 launches, so the 6th = first AG GEMM gets ncu's -s 5 -c 1)
    init_state<<<(Ss * Bsz * Hh + 255) / 256, blk>>>(hid0, cur0, hsp, hf, c);
    conv_x<<<(Bsz * Dd + 255) / 256, blk>>>(x, xsp);
    repack_all<<<(RW5 + 255) / 256, blk>>>(Wi_f, Wi_i, Wi_o, Wi_c,
                                           Wh_f, Wh_i, Wh_o, Wh_c,
                                           bi_f, bi_i, bi_o, bi_c,
                                           bh_f, bh_i, bh_o,
                                           WiAll, Whfio, Whc, biAll, bhfio);
    glog0_kernel<<<(Bsz * 3 * 32 + 255) / 256, blk>>>(x, Wi_g, bi_g, G0);
    // time-invariant layer-0 input preacts
    gemm256<<<dim3(4, 32, 1), blk, SMEM_GEMM>>>(xsp, Dd, 0L,
                                                WiAll, 0L, biAll, 0,
                                                Z0, NZS, 0L, Dd);

    for (int t = 0; t < REPT; t++) {
        // AG = h_cat @ WhcSlim^T + bh_c  (fused over layers, N=2304 exact)
        gemm256<<<dim3(9, 32, 1), blk, SMEM_GEMM>>>(hsp, SH, 0L,
                                                    Whc, 0L, bh_c, 0,
                                                    AG, NAG, 0L, SH);
        // U[l] = h_prev[l] @ [Wh_f;Wh_i;Wh_o][l]^T + bias  (batched over l)
        gemm256<<<dim3(3, 32, 3), blk, SMEM_GEMM>>>(hsp, SH, (long)Hh,
                                                    Whfio, (long)NU * Hh, bhfio, NU,
                                                    U, NU, (long)Bsz * NU, Hh);
        // G2 = Wh_g . h_cat + bh_g
        glog2_kernel<<<(Bsz * 9 * 32 + 255) / 256, blk>>>(hf, Wh_g, bh_g, G2);

        for (int l = 0; l < Ss; l++) {
            const float* Zl = Z0;
            if (l > 0) {
                gemm256<<<dim3(4, 32, 1), blk, SMEM_GEMM>>>(
                    hsp + (size_t)(l - 1) * Hh, SH, 0L,
                    WiAll + (size_t)l * NZS * Dd, 0L,
                    biAll + l * NZS, 0,
                    Z, NZS, 0L, Hh);
                Zl = Z;
            }
            float* fptr = (l == Ss - 1 && t < REPT - 1) ? featf : nullptr;
            cell_kernel<<<Bsz, blk>>>(
                Zl, U + (size_t)l * Bsz * NU, AG, G2, G0,
                Wi_g + (size_t)l * 3 * Dd, bi_g + l * 3,
                (l > 0) ? (hf + (size_t)(l - 1) * Hh) : nullptr,
                hsp, hf, c, fptr, l, t);
        }
    }

    out_kernel<<<(Bsz * OUTN * 32 + 255) / 256, blk>>>(featf, W_last, b_last, out);
}